// round 11
// baseline (speedup 1.0000x reference)
#include <cuda_runtime.h>
#include <cuda_fp16.h>
#include <cstdint>

#define Bsz 4
#define Cch 512
#define MID 64
#define HWc 16384
#define PROJ_M 640
#define NEGV (-1e30f)

// ---------------- scratch ----------------------------------------------------
__device__ __align__(16) __half g_xh  [(size_t)Bsz*Cch*HWc];
__device__ __align__(16) __half g_wall[PROJ_M*Cch];
__device__ __align__(16) __half g_proj [(size_t)Bsz*PROJ_M*HWc];
__device__ __align__(16) __half g_projT[(size_t)Bsz*PROJ_M*HWc];
__device__ __align__(16) float  g_eH[(size_t)Bsz*128*HWc];
__device__ __align__(16) float  g_eW[(size_t)Bsz*128*HWc];
__device__ __align__(16) __half g_aH[(size_t)Bsz*128*HWc];
__device__ __align__(16) __half g_aW[(size_t)Bsz*128*HWc];
__device__ __align__(16) __half g_oHt[(size_t)Bsz*Cch*HWc];
__device__ __align__(16) __half g_oW [(size_t)Bsz*Cch*HWc];

// ---------------- helpers ------------------------------------------------------
__device__ __forceinline__ uint32_t sptr(const void* p){
    return (uint32_t)__cvta_generic_to_shared(p);
}
__device__ __forceinline__ void cpa16(uint32_t s, const void* g){
    asm volatile("cp.async.ca.shared.global [%0], [%1], 16;" :: "r"(s), "l"(g));
}
#define CP_COMMIT() asm volatile("cp.async.commit_group;")
#define CP_WAIT(n)  asm volatile("cp.async.wait_group %0;" :: "n"(n))

__device__ __forceinline__ void ldsm4(uint32_t* r, uint32_t a){
    asm volatile("ldmatrix.sync.aligned.m8n8.x4.shared.b16 {%0,%1,%2,%3},[%4];"
        : "=r"(r[0]),"=r"(r[1]),"=r"(r[2]),"=r"(r[3]) : "r"(a));
}
__device__ __forceinline__ void ldsm4t(uint32_t* r, uint32_t a){
    asm volatile("ldmatrix.sync.aligned.m8n8.x4.trans.shared.b16 {%0,%1,%2,%3},[%4];"
        : "=r"(r[0]),"=r"(r[1]),"=r"(r[2]),"=r"(r[3]) : "r"(a));
}
__device__ __forceinline__ void mma_f16(float* c, const uint32_t* a, uint32_t b0, uint32_t b1){
    asm volatile(
        "mma.sync.aligned.m16n8k16.row.col.f32.f16.f16.f32 "
        "{%0,%1,%2,%3}, {%4,%5,%6,%7}, {%8,%9}, {%0,%1,%2,%3};"
        : "+f"(c[0]),"+f"(c[1]),"+f"(c[2]),"+f"(c[3])
        : "r"(a[0]),"r"(a[1]),"r"(a[2]),"r"(a[3]),"r"(b0),"r"(b1));
}
__device__ __forceinline__ uint2 f4_to_h4(float4 v){
    __half2 a = __floats2half2_rn(v.x, v.y);
    __half2 b = __floats2half2_rn(v.z, v.w);
    uint2 u; u.x = *(uint32_t*)&a; u.y = *(uint32_t*)&b; return u;
}

// ---------------- conversions --------------------------------------------------
__global__ void convert_x(const float* __restrict__ x, __half* __restrict__ xh){
    size_t i = ((size_t)blockIdx.x*256 + threadIdx.x)*4;
    *(uint2*)(xh + i) = f4_to_h4(*(const float4*)(x + i));
}
__global__ void pack_w(const float* __restrict__ Wq, const float* __restrict__ Wk,
                       const float* __restrict__ Wv, __half* __restrict__ wall){
    int i = (blockIdx.x*256 + threadIdx.x)*4;
    int row = i >> 9, col = i & 511;
    const float* src = row < 64 ? Wq + (size_t)row*512
                     : row < 128 ? Wk + (size_t)(row-64)*512
                                 : Wv + (size_t)(row-128)*512;
    *(uint2*)(wall + i) = f4_to_h4(*(const float4*)(src + col));
}

// ---------------- projection: proj[b] = Wall(640x512) @ xh[b](512x16384) -----
// block 128m x 256n, BK=32, 3-stage cp.async (dynamic smem 80KB);
// 8 warps (2m x 4n), warp tile 64x64: 8 LDSM per 32 HMMA.
#define PROJ_AS (128*40)            // halves per A stage
#define PROJ_BS (32*264)            // halves per B stage
#define PROJ_SMEM ((3*PROJ_AS + 3*PROJ_BS)*2)

__global__ void __launch_bounds__(256) proj_f16(
        const __half* __restrict__ Wall, const __half* __restrict__ xh,
        __half* __restrict__ Out){
    extern __shared__ __half sm[];
    __half* As = sm;                    // 3 stages of [128][40]
    __half* Bs = sm + 3*PROJ_AS;        // 3 stages of [32][264]

    const int b = blockIdx.z;
    const int m0blk = blockIdx.y * 128;
    const __half* Bg = xh + (size_t)b*Cch*HWc + blockIdx.x*256;
    __half* Cg = Out + ((size_t)b*PROJ_M + m0blk)*HWc + blockIdx.x*256;

    const int tid = threadIdx.x, lane = tid & 31, warp = tid >> 5;
    const int wr = warp >> 2, wc = warp & 3;

    // A: 512 chunks (2/thr), B: 1024 chunks (4/thr)
    const __half* asrc[2]; const __half* bsrc[4];
    uint32_t adst[3][2], bdst[3][4];
    #pragma unroll
    for (int i = 0; i < 2; i++){
        int e = tid + i*256;
        int ra = e >> 2, ca = e & 3;
        asrc[i] = Wall + (size_t)(m0blk + ra)*Cch + ca*8;
        #pragma unroll
        for (int s = 0; s < 3; s++)
            adst[s][i] = sptr(As + s*PROJ_AS + ra*40 + ca*8);
    }
    #pragma unroll
    for (int i = 0; i < 4; i++){
        int e = tid + i*256;
        int rb = e >> 5, cb = e & 31;
        bsrc[i] = Bg + (size_t)rb*HWc + cb*8;
        #pragma unroll
        for (int s = 0; s < 3; s++)
            bdst[s][i] = sptr(Bs + s*PROJ_BS + rb*264 + cb*8);
    }

    float acc[4][8][4] = {};
    const int NIT = Cch/32;   // 16

    #pragma unroll
    for (int s = 0; s < 2; s++){
        const int k0 = s*32;
        #pragma unroll
        for (int i = 0; i < 2; i++) cpa16(adst[s][i], asrc[i] + k0);
        #pragma unroll
        for (int i = 0; i < 4; i++) cpa16(bdst[s][i], bsrc[i] + (size_t)k0*HWc);
        CP_COMMIT();
    }

    for (int it = 0; it < NIT; it++){
        if (it == NIT-1) { CP_WAIT(0); } else { CP_WAIT(1); }
        __syncthreads();
        if (it + 2 < NIT){
            const int s = (it+2) % 3;
            const int k0 = (it+2)*32;
            #pragma unroll
            for (int i = 0; i < 2; i++) cpa16(adst[s][i], asrc[i] + k0);
            #pragma unroll
            for (int i = 0; i < 4; i++) cpa16(bdst[s][i], bsrc[i] + (size_t)k0*HWc);
            CP_COMMIT();
        }
        const __half* Ac = As + (it % 3)*PROJ_AS;
        const __half* Bc = Bs + (it % 3)*PROJ_BS;
        #pragma unroll
        for (int ks = 0; ks < 2; ks++){
            uint32_t af[4][4], bfm[4][4];
            #pragma unroll
            for (int mt = 0; mt < 4; mt++){
                int row = wr*64 + mt*16 + (lane & 7) + ((lane >> 3) & 1)*8;
                int col = ks*16 + (lane >> 4)*8;
                ldsm4(af[mt], sptr(Ac + row*40 + col));
            }
            #pragma unroll
            for (int p = 0; p < 4; p++){
                int krow = ks*16 + ((lane >> 3) & 1)*8 + (lane & 7);
                int ncol = wc*64 + p*16 + (lane >> 4)*8;
                ldsm4t(bfm[p], sptr(Bc + krow*264 + ncol));
            }
            #pragma unroll
            for (int mt = 0; mt < 4; mt++)
                #pragma unroll
                for (int nt = 0; nt < 8; nt++)
                    mma_f16(acc[mt][nt], af[mt], bfm[nt>>1][(nt&1)*2], bfm[nt>>1][(nt&1)*2+1]);
        }
    }
    __syncthreads();
    #pragma unroll
    for (int mt = 0; mt < 4; mt++)
        #pragma unroll
        for (int nt = 0; nt < 8; nt++){
            int row = wr*64 + mt*16 + (lane >> 2);
            int col = wc*64 + nt*8 + (lane & 3)*2;
            __half2 u0 = __floats2half2_rn(acc[mt][nt][0], acc[mt][nt][1]);
            __half2 u1 = __floats2half2_rn(acc[mt][nt][2], acc[mt][nt][3]);
            *(__half2*)(Cg + (size_t)row*HWc + col)     = u0;
            *(__half2*)(Cg + (size_t)(row+8)*HWc + col) = u1;
        }
}

// ---------------- 128x128 fp16 plane transpose (64x64 tiles) ------------------
__global__ void transpose_f16(const __half* __restrict__ in, __half* __restrict__ out){
    __shared__ __half t[64][65];
    const size_t p = blockIdx.z;
    const __half* ip = in + p*HWc;
    __half* op = out + p*HWc;
    const int x0 = blockIdx.x*64, y0 = blockIdx.y*64;
    const int tx = threadIdx.x & 15, ty = threadIdx.x >> 4;
    #pragma unroll
    for (int r = 0; r < 64; r += 16){
        uint2 u = *(const uint2*)(ip + (size_t)(y0+ty+r)*128 + x0 + tx*4);
        __half2 lo = *(__half2*)&u.x, hi = *(__half2*)&u.y;
        __half* d = &t[ty+r][tx*4];
        d[0]=lo.x; d[1]=lo.y; d[2]=hi.x; d[3]=hi.y;
    }
    __syncthreads();
    #pragma unroll
    for (int r = 0; r < 64; r += 16){
        __half2 lo, hi;
        lo.x = t[tx*4+0][ty+r]; lo.y = t[tx*4+1][ty+r];
        hi.x = t[tx*4+2][ty+r]; hi.y = t[tx*4+3][ty+r];
        uint2 u; u.x = *(uint32_t*)&lo; u.y = *(uint32_t*)&hi;
        *(uint2*)(op + (size_t)(x0+ty+r)*128 + y0 + tx*4) = u;
    }
}

// ---------------- gram: E[i,j] = sum_m Q[m,i]*K[m,j], 2-stage preissued -------
__global__ void gram_f16(const __half* __restrict__ proj, const __half* __restrict__ projT,
                         float* __restrict__ eH, float* __restrict__ eW){
    const __half* P = blockIdx.y ? proj : projT;
    float* E = blockIdx.y ? eW : eH;
    const int bl = blockIdx.x, b = bl >> 7, line = bl & 127;
    const __half* qb = P + (size_t)(b*PROJ_M)*HWc + line*128;
    const __half* kb = qb + (size_t)MID*HWc;

    __shared__ __half Qs[2][32*136];
    __shared__ __half Ks[2][32*136];

    const int tid = threadIdx.x, lane = tid & 31, warp = tid >> 5;
    const int wr = warp >> 1, wc = warp & 1;

    #pragma unroll
    for (int s = 0; s < 2; s++){
        #pragma unroll
        for (int i = 0; i < 2; i++){
            int e = tid + i*256, r = e >> 4, c = e & 15;
            cpa16(sptr(&Qs[s][r*136 + c*8]), qb + (size_t)(s*32+r)*HWc + c*8);
            cpa16(sptr(&Ks[s][r*136 + c*8]), kb + (size_t)(s*32+r)*HWc + c*8);
        }
        CP_COMMIT();
    }

    float acc[2][8][4] = {};

    #pragma unroll
    for (int st = 0; st < 2; st++){
        if (st == 0) { CP_WAIT(1); } else { CP_WAIT(0); }
        __syncthreads();
        const __half* Qc = Qs[st];
        const __half* Kc = Ks[st];
        #pragma unroll
        for (int ks = 0; ks < 2; ks++){
            uint32_t af[2][4], bfm[4][4];
            #pragma unroll
            for (int mt = 0; mt < 2; mt++){
                int row = ks*16 + (lane >> 4)*8 + (lane & 7);
                int col = wr*32 + mt*16 + ((lane >> 3) & 1)*8;
                ldsm4t(af[mt], sptr(Qc + row*136 + col));
            }
            #pragma unroll
            for (int p = 0; p < 4; p++){
                int krow = ks*16 + ((lane >> 3) & 1)*8 + (lane & 7);
                int ncol = wc*64 + p*16 + (lane >> 4)*8;
                ldsm4t(bfm[p], sptr(Kc + krow*136 + ncol));
            }
            #pragma unroll
            for (int mt = 0; mt < 2; mt++)
                #pragma unroll
                for (int nt = 0; nt < 8; nt++)
                    mma_f16(acc[mt][nt], af[mt], bfm[nt>>1][(nt&1)*2], bfm[nt>>1][(nt&1)*2+1]);
        }
    }
    float* eb = E + (size_t)bl*HWc;
    #pragma unroll
    for (int mt = 0; mt < 2; mt++)
        #pragma unroll
        for (int nt = 0; nt < 8; nt++){
            int row = wr*32 + mt*16 + (lane >> 2);
            int col = wc*64 + nt*8 + (lane & 3)*2;
            float2 u0 = { acc[mt][nt][0], acc[mt][nt][1] };
            float2 u1 = { acc[mt][nt][2], acc[mt][nt][3] };
            *(float2*)&eb[(size_t)row*128 + col]     = u0;
            *(float2*)&eb[(size_t)(row+8)*128 + col] = u1;
        }
}

// ---------------- joint softmax, fp32 in -> fp16 probs out --------------------
__global__ void softmax_kernel(const float* __restrict__ eH, const float* __restrict__ eW,
                               __half* __restrict__ aH, __half* __restrict__ aW){
    const int pix  = blockIdx.x*8 + (threadIdx.x >> 5);
    const int lane = threadIdx.x & 31;
    const int w = pix & 127, h = (pix >> 7) & 127, b = pix >> 14;

    const size_t offH = ((size_t)((b*128 + w)*128 + h))*128 + lane*4;
    const size_t offW = ((size_t)((b*128 + h)*128 + w))*128 + lane*4;
    float4 vh = *(const float4*)(eH + offH);
    float4 vw = *(const float4*)(eW + offW);

    const int d = h - lane*4;
    if (d >= 0 && d < 4) ((float*)&vh)[d] = NEGV;

    float mx = fmaxf(fmaxf(fmaxf(vh.x, vh.y), fmaxf(vh.z, vh.w)),
                     fmaxf(fmaxf(vw.x, vw.y), fmaxf(vw.z, vw.w)));
    #pragma unroll
    for (int o = 16; o; o >>= 1) mx = fmaxf(mx, __shfl_xor_sync(0xffffffffu, mx, o));

    vh.x = __expf(vh.x - mx); vh.y = __expf(vh.y - mx);
    vh.z = __expf(vh.z - mx); vh.w = __expf(vh.w - mx);
    vw.x = __expf(vw.x - mx); vw.y = __expf(vw.y - mx);
    vw.z = __expf(vw.z - mx); vw.w = __expf(vw.w - mx);

    float s = vh.x + vh.y + vh.z + vh.w + vw.x + vw.y + vw.z + vw.w;
    #pragma unroll
    for (int o = 16; o; o >>= 1) s += __shfl_xor_sync(0xffffffffu, s, o);
    const float inv = 1.0f / s;

    float4 ph = { vh.x*inv, vh.y*inv, vh.z*inv, vh.w*inv };
    float4 pw = { vw.x*inv, vw.y*inv, vw.z*inv, vw.w*inv };
    *(uint2*)(aH + offH) = f4_to_h4(ph);
    *(uint2*)(aW + offW) = f4_to_h4(pw);
}

// ---------------- apply: Out[c,i] = sum_j V[c,j]*P[i,j] -----------------------
// block 256c x 128i, BK=32, 3-stage cp.async (dynamic smem 90KB);
// 8 warps (4m x 2n), warp tile 64x64.
// blockIdx.z: 0 -> (projT, aH) -> oHt ; 1 -> (proj, aW) -> oW
#define APPLY_VS (256*40)
#define APPLY_PS (128*40)
#define APPLY_SMEM ((3*APPLY_VS + 3*APPLY_PS)*2)

__global__ void __launch_bounds__(256) apply_f16(
        const __half* __restrict__ proj, const __half* __restrict__ projT,
        const __half* __restrict__ aH, const __half* __restrict__ aW,
        __half* __restrict__ oHt, __half* __restrict__ oW){
    extern __shared__ __half sm[];
    __half* Vs = sm;                    // 3 stages of [256][40]
    __half* Ps = sm + 3*APPLY_VS;       // 3 stages of [128][40]

    const __half* Vfull = blockIdx.z ? proj : projT;
    const __half* Pm    = blockIdx.z ? aW : aH;
    __half* Outp        = blockIdx.z ? oW : oHt;

    const int bl = blockIdx.y, b = bl >> 7, line = bl & 127;
    const __half* Vb = Vfull + ((size_t)(b*PROJ_M + 128 + blockIdx.x*256))*HWc + line*128;
    const __half* Pb = Pm + (size_t)bl*HWc;
    __half* Ob = Outp + ((size_t)(b*Cch + blockIdx.x*256))*HWc + line*128;

    const int tid = threadIdx.x, lane = tid & 31, warp = tid >> 5;
    const int wr = warp >> 1, wc = warp & 1;

    // V: 1024 chunks (4/thr), P: 512 chunks (2/thr)
    const __half* vsrc[4]; const __half* psrc[2];
    uint32_t vdst[3][4], pdst[3][2];
    #pragma unroll
    for (int i = 0; i < 4; i++){
        int e = tid + i*256;
        int r = e >> 2, c = e & 3;
        vsrc[i] = Vb + (size_t)r*HWc + c*8;
        #pragma unroll
        for (int s = 0; s < 3; s++)
            vdst[s][i] = sptr(Vs + s*APPLY_VS + r*40 + c*8);
    }
    #pragma unroll
    for (int i = 0; i < 2; i++){
        int e = tid + i*256;
        int r = e >> 2, c = e & 3;
        psrc[i] = Pb + (size_t)r*128 + c*8;
        #pragma unroll
        for (int s = 0; s < 3; s++)
            pdst[s][i] = sptr(Ps + s*APPLY_PS + r*40 + c*8);
    }

    float acc[4][8][4] = {};
    const int NIT = 128/32;   // 4

    #pragma unroll
    for (int s = 0; s < 2; s++){
        #pragma unroll
        for (int i = 0; i < 4; i++) cpa16(vdst[s][i], vsrc[i] + s*32);
        #pragma unroll
        for (int i = 0; i < 2; i++) cpa16(pdst[s][i], psrc[i] + s*32);
        CP_COMMIT();
    }

    for (int it = 0; it < NIT; it++){
        if (it == NIT-1) { CP_WAIT(0); } else { CP_WAIT(1); }
        __syncthreads();
        if (it + 2 < NIT){
            const int s = (it+2) % 3;
            const int j0 = (it+2)*32;
            #pragma unroll
            for (int i = 0; i < 4; i++) cpa16(vdst[s][i], vsrc[i] + j0);
            #pragma unroll
            for (int i = 0; i < 2; i++) cpa16(pdst[s][i], psrc[i] + j0);
            CP_COMMIT();
        }
        const __half* Vc = Vs + (it % 3)*APPLY_VS;
        const __half* Pc = Ps + (it % 3)*APPLY_PS;
        #pragma unroll
        for (int ks = 0; ks < 2; ks++){
            uint32_t af[4][4], bfm[4][4];
            #pragma unroll
            for (int mt = 0; mt < 4; mt++){
                int row = wr*64 + mt*16 + (lane & 7) + ((lane >> 3) & 1)*8;
                int col = ks*16 + (lane >> 4)*8;
                ldsm4(af[mt], sptr(Vc + row*40 + col));
            }
            #pragma unroll
            for (int p = 0; p < 4; p++){
                int prow = wc*64 + p*16 + (lane >> 4)*8 + (lane & 7);   // B non-trans
                int pcol = ks*16 + ((lane >> 3) & 1)*8;
                ldsm4(bfm[p], sptr(Pc + prow*40 + pcol));
            }
            #pragma unroll
            for (int mt = 0; mt < 4; mt++)
                #pragma unroll
                for (int nt = 0; nt < 8; nt++)
                    mma_f16(acc[mt][nt], af[mt], bfm[nt>>1][(nt&1)*2], bfm[nt>>1][(nt&1)*2+1]);
        }
    }
    __syncthreads();
    #pragma unroll
    for (int mt = 0; mt < 4; mt++)
        #pragma unroll
        for (int nt = 0; nt < 8; nt++){
            int row = wr*64 + mt*16 + (lane >> 2);
            int col = wc*64 + nt*8 + (lane & 3)*2;
            __half2 u0 = __floats2half2_rn(acc[mt][nt][0], acc[mt][nt][1]);
            __half2 u1 = __floats2half2_rn(acc[mt][nt][2], acc[mt][nt][3]);
            *(__half2*)(Ob + (size_t)row*HWc + col)     = u0;
            *(__half2*)(Ob + (size_t)(row+8)*HWc + col) = u1;
        }
}

// ---------------- combine: out = gamma*(oHt^T + oW) + x ------------------------
__global__ void combine_kernel(const __half* __restrict__ oHt, const __half* __restrict__ oW,
                               const float* __restrict__ x, const float* __restrict__ gamma,
                               float* __restrict__ out){
    __shared__ __half t[64][65];
    const size_t p = blockIdx.z;
    const __half* hp = oHt + p*HWc;
    const int w0 = blockIdx.x*64, h0 = blockIdx.y*64;
    const int tx = threadIdx.x & 15, ty = threadIdx.x >> 4;
    #pragma unroll
    for (int r = 0; r < 64; r += 16){
        uint2 u = *(const uint2*)(hp + (size_t)(w0+ty+r)*128 + h0 + tx*4);
        __half2 lo = *(__half2*)&u.x, hi = *(__half2*)&u.y;
        __half* d = &t[ty+r][tx*4];
        d[0]=lo.x; d[1]=lo.y; d[2]=hi.x; d[3]=hi.y;
    }
    __syncthreads();
    const float g = gamma[0];
    #pragma unroll
    for (int r = 0; r < 64; r += 16){
        const int h = h0 + ty + r;
        const size_t base = p*HWc + (size_t)h*128 + w0 + tx*4;
        float4 xr = *(const float4*)(x + base);
        uint2 uw = *(const uint2*)(oW + base);
        __half2 lo = *(__half2*)&uw.x, hi = *(__half2*)&uw.y;
        float4 o;
        o.x = g*(__half2float(t[tx*4+0][ty+r]) + __half2float(lo.x)) + xr.x;
        o.y = g*(__half2float(t[tx*4+1][ty+r]) + __half2float(lo.y)) + xr.y;
        o.z = g*(__half2float(t[tx*4+2][ty+r]) + __half2float(hi.x)) + xr.z;
        o.w = g*(__half2float(t[tx*4+3][ty+r]) + __half2float(hi.y)) + xr.w;
        *(float4*)(out + base) = o;
    }
}

// ---------------------------------------------------------------------------
extern "C" void kernel_launch(void* const* d_in, const int* in_sizes, int n_in,
                              void* d_out, int out_size) {
    (void)in_sizes; (void)n_in; (void)out_size;
    const float* x     = (const float*)d_in[0];
    const float* Wq    = (const float*)d_in[1];
    const float* Wk    = (const float*)d_in[2];
    const float* Wv    = (const float*)d_in[3];
    const float* gamma = (const float*)d_in[4];
    float* out = (float*)d_out;

    __half *xh, *wall, *proj, *projT, *aH, *aW, *oHt, *oW;
    float *eH, *eW;
    cudaGetSymbolAddress((void**)&xh,   g_xh);
    cudaGetSymbolAddress((void**)&wall, g_wall);
    cudaGetSymbolAddress((void**)&proj, g_proj);
    cudaGetSymbolAddress((void**)&projT,g_projT);
    cudaGetSymbolAddress((void**)&eH,   g_eH);
    cudaGetSymbolAddress((void**)&eW,   g_eW);
    cudaGetSymbolAddress((void**)&aH,   g_aH);
    cudaGetSymbolAddress((void**)&aW,   g_aW);
    cudaGetSymbolAddress((void**)&oHt,  g_oHt);
    cudaGetSymbolAddress((void**)&oW,   g_oW);

    cudaFuncSetAttribute(proj_f16,  cudaFuncAttributeMaxDynamicSharedMemorySize, PROJ_SMEM);
    cudaFuncSetAttribute(apply_f16, cudaFuncAttributeMaxDynamicSharedMemorySize, APPLY_SMEM);

    // 0) fp16 conversion + weight packing
    convert_x<<<(Bsz*Cch*HWc)/(256*4), 256>>>(x, xh);
    pack_w<<<(PROJ_M*Cch)/(256*4), 256>>>(Wq, Wk, Wv, wall);

    // 1) fused projection (q|k|v packed), fp16 HMMA, 64x64 warp tiles
    proj_f16<<<dim3(HWc/256, PROJ_M/128, Bsz), 256, PROJ_SMEM>>>(wall, xh, proj);

    // 2) plane transposes (H<->W for all 640 planes per batch), fp16
    transpose_f16<<<dim3(2,2,Bsz*PROJ_M), 256>>>(proj, projT);

    // 3) attention scores (y=0: eH from projT, y=1: eW from proj), fp32 out
    gram_f16<<<dim3(Bsz*128, 2), 256>>>(proj, projT, eH, eW);

    // 4) joint softmax -> fp16 probs
    softmax_kernel<<<(Bsz*HWc)/8, 256>>>(eH, eW, aH, aW);

    // 5) apply attention (z=0 -> oHt, z=1 -> oW), 64x64 warp tiles
    apply_f16<<<dim3(Cch/256, Bsz*128, 2), 256, APPLY_SMEM>>>(proj, projT, aH, aW, oHt, oW);

    // 6) combine
    combine_kernel<<<dim3(2,2,Bsz*Cch), 256>>>(oHt, oW, x, gamma, out);
}

// round 12
// speedup vs baseline: 1.0910x; 1.0910x over previous
#include <cuda_runtime.h>
#include <cuda_fp16.h>
#include <cstdint>

#define Bsz 4
#define Cch 512
#define MID 64
#define HWc 16384
#define PROJ_M 640
#define NEGV (-1e30f)

// ---------------- scratch ----------------------------------------------------
__device__ __align__(16) __half g_xh  [(size_t)Bsz*Cch*HWc];
__device__ __align__(16) __half g_wall[PROJ_M*Cch];
__device__ __align__(16) __half g_proj [(size_t)Bsz*PROJ_M*HWc];
__device__ __align__(16) __half g_projT[(size_t)Bsz*PROJ_M*HWc];
__device__ __align__(16) float  g_eH[(size_t)Bsz*128*HWc];
__device__ __align__(16) float  g_eW[(size_t)Bsz*128*HWc];
__device__ __align__(16) __half g_aH[(size_t)Bsz*128*HWc];
__device__ __align__(16) __half g_aW[(size_t)Bsz*128*HWc];
__device__ __align__(16) __half g_oHt[(size_t)Bsz*Cch*HWc];
__device__ __align__(16) __half g_oW [(size_t)Bsz*Cch*HWc];

// ---------------- helpers ------------------------------------------------------
__device__ __forceinline__ uint32_t sptr(const void* p){
    return (uint32_t)__cvta_generic_to_shared(p);
}
__device__ __forceinline__ void cpa16(uint32_t s, const void* g){
    asm volatile("cp.async.ca.shared.global [%0], [%1], 16;" :: "r"(s), "l"(g));
}
#define CP_COMMIT() asm volatile("cp.async.commit_group;")
#define CP_WAIT(n)  asm volatile("cp.async.wait_group %0;" :: "n"(n))

__device__ __forceinline__ void ldsm4(uint32_t* r, uint32_t a){
    asm volatile("ldmatrix.sync.aligned.m8n8.x4.shared.b16 {%0,%1,%2,%3},[%4];"
        : "=r"(r[0]),"=r"(r[1]),"=r"(r[2]),"=r"(r[3]) : "r"(a));
}
__device__ __forceinline__ void ldsm4t(uint32_t* r, uint32_t a){
    asm volatile("ldmatrix.sync.aligned.m8n8.x4.trans.shared.b16 {%0,%1,%2,%3},[%4];"
        : "=r"(r[0]),"=r"(r[1]),"=r"(r[2]),"=r"(r[3]) : "r"(a));
}
__device__ __forceinline__ void mma_f16(float* c, const uint32_t* a, uint32_t b0, uint32_t b1){
    asm volatile(
        "mma.sync.aligned.m16n8k16.row.col.f32.f16.f16.f32 "
        "{%0,%1,%2,%3}, {%4,%5,%6,%7}, {%8,%9}, {%0,%1,%2,%3};"
        : "+f"(c[0]),"+f"(c[1]),"+f"(c[2]),"+f"(c[3])
        : "r"(a[0]),"r"(a[1]),"r"(a[2]),"r"(a[3]),"r"(b0),"r"(b1));
}
__device__ __forceinline__ uint2 f4_to_h4(float4 v){
    __half2 a = __floats2half2_rn(v.x, v.y);
    __half2 b = __floats2half2_rn(v.z, v.w);
    uint2 u; u.x = *(uint32_t*)&a; u.y = *(uint32_t*)&b; return u;
}

// ---------------- conversions --------------------------------------------------
__global__ void convert_x(const float* __restrict__ x, __half* __restrict__ xh){
    size_t i = ((size_t)blockIdx.x*256 + threadIdx.x)*4;
    *(uint2*)(xh + i) = f4_to_h4(*(const float4*)(x + i));
}
__global__ void pack_w(const float* __restrict__ Wq, const float* __restrict__ Wk,
                       const float* __restrict__ Wv, __half* __restrict__ wall){
    int i = (blockIdx.x*256 + threadIdx.x)*4;
    int row = i >> 9, col = i & 511;
    const float* src = row < 64 ? Wq + (size_t)row*512
                     : row < 128 ? Wk + (size_t)(row-64)*512
                                 : Wv + (size_t)(row-128)*512;
    *(uint2*)(wall + i) = f4_to_h4(*(const float4*)(src + col));
}

// ---------------- projection: proj[b] = Wall(640x512) @ xh[b](512x16384) -----
// block 128m x 128n, BK=32, 3-stage cp.async; 8 warps (4x2), warp tile 32x64.
__global__ void proj_f16(const __half* __restrict__ Wall, const __half* __restrict__ xh,
                         __half* __restrict__ Out){
    const int b = blockIdx.z;
    const int m0blk = blockIdx.y * 128;
    const __half* Bg = xh + (size_t)b*Cch*HWc + blockIdx.x*128;
    __half* Cg = Out + ((size_t)b*PROJ_M + m0blk)*HWc + blockIdx.x*128;

    __shared__ __half As[3][128*40];   // [m][k] stride 40
    __shared__ __half Bs[3][32*136];   // [k][n] stride 136

    const int tid = threadIdx.x, lane = tid & 31, warp = tid >> 5;
    const int wr = warp >> 1, wc = warp & 1;

    const __half* asrc[2]; const __half* bsrc[2];
    uint32_t adst[3][2], bdst[3][2];
    #pragma unroll
    for (int i = 0; i < 2; i++){
        int e = tid + i*256;
        int ra = e >> 2, ca = e & 3;               // A: 4 chunks per 32-half row
        asrc[i] = Wall + (size_t)(m0blk + ra)*Cch + ca*8;
        int rb = e >> 4, cb = e & 15;              // B: 16 chunks per 128-half row
        bsrc[i] = Bg + (size_t)rb*HWc + cb*8;
        #pragma unroll
        for (int s = 0; s < 3; s++){
            adst[s][i] = sptr(&As[s][ra*40 + ca*8]);
            bdst[s][i] = sptr(&Bs[s][rb*136 + cb*8]);
        }
    }

    float acc[2][8][4] = {};
    const int NIT = Cch/32;   // 16

    #pragma unroll
    for (int s = 0; s < 2; s++){
        const int k0 = s*32;
        #pragma unroll
        for (int i = 0; i < 2; i++){
            cpa16(adst[s][i], asrc[i] + k0);
            cpa16(bdst[s][i], bsrc[i] + (size_t)k0*HWc);
        }
        CP_COMMIT();
    }

    for (int it = 0; it < NIT; it++){
        if (it == NIT-1) { CP_WAIT(0); } else { CP_WAIT(1); }
        __syncthreads();
        if (it + 2 < NIT){
            const int s = (it+2) % 3;
            const int k0 = (it+2)*32;
            #pragma unroll
            for (int i = 0; i < 2; i++){
                cpa16(adst[s][i], asrc[i] + k0);
                cpa16(bdst[s][i], bsrc[i] + (size_t)k0*HWc);
            }
            CP_COMMIT();
        }
        const __half* Ac = As[it % 3];
        const __half* Bc = Bs[it % 3];
        #pragma unroll
        for (int ks = 0; ks < 2; ks++){
            uint32_t af[2][4], bfm[4][4];
            #pragma unroll
            for (int mt = 0; mt < 2; mt++){
                int row = wr*32 + mt*16 + (lane & 7) + ((lane >> 3) & 1)*8;
                int col = ks*16 + (lane >> 4)*8;
                ldsm4(af[mt], sptr(Ac + row*40 + col));
            }
            #pragma unroll
            for (int p = 0; p < 4; p++){
                int krow = ks*16 + ((lane >> 3) & 1)*8 + (lane & 7);
                int ncol = wc*64 + p*16 + (lane >> 4)*8;
                ldsm4t(bfm[p], sptr(Bc + krow*136 + ncol));
            }
            #pragma unroll
            for (int mt = 0; mt < 2; mt++)
                #pragma unroll
                for (int nt = 0; nt < 8; nt++)
                    mma_f16(acc[mt][nt], af[mt], bfm[nt>>1][(nt&1)*2], bfm[nt>>1][(nt&1)*2+1]);
        }
    }
    __syncthreads();
    #pragma unroll
    for (int mt = 0; mt < 2; mt++)
        #pragma unroll
        for (int nt = 0; nt < 8; nt++){
            int row = wr*32 + mt*16 + (lane >> 2);
            int col = wc*64 + nt*8 + (lane & 3)*2;
            __half2 u0 = __floats2half2_rn(acc[mt][nt][0], acc[mt][nt][1]);
            __half2 u1 = __floats2half2_rn(acc[mt][nt][2], acc[mt][nt][3]);
            *(__half2*)(Cg + (size_t)row*HWc + col)     = u0;
            *(__half2*)(Cg + (size_t)(row+8)*HWc + col) = u1;
        }
}

// ---------------- 128x128 fp16 plane transpose (64x64 tiles) ------------------
__global__ void transpose_f16(const __half* __restrict__ in, __half* __restrict__ out){
    __shared__ __half t[64][65];
    const size_t p = blockIdx.z;
    const __half* ip = in + p*HWc;
    __half* op = out + p*HWc;
    const int x0 = blockIdx.x*64, y0 = blockIdx.y*64;
    const int tx = threadIdx.x & 15, ty = threadIdx.x >> 4;
    #pragma unroll
    for (int r = 0; r < 64; r += 16){
        uint2 u = *(const uint2*)(ip + (size_t)(y0+ty+r)*128 + x0 + tx*4);
        __half2 lo = *(__half2*)&u.x, hi = *(__half2*)&u.y;
        __half* d = &t[ty+r][tx*4];
        d[0]=lo.x; d[1]=lo.y; d[2]=hi.x; d[3]=hi.y;
    }
    __syncthreads();
    #pragma unroll
    for (int r = 0; r < 64; r += 16){
        __half2 lo, hi;
        lo.x = t[tx*4+0][ty+r]; lo.y = t[tx*4+1][ty+r];
        hi.x = t[tx*4+2][ty+r]; hi.y = t[tx*4+3][ty+r];
        uint2 u; u.x = *(uint32_t*)&lo; u.y = *(uint32_t*)&hi;
        *(uint2*)(op + (size_t)(x0+ty+r)*128 + y0 + tx*4) = u;
    }
}

// ---------------- gram: E[i,j] = sum_m Q[m,i]*K[m,j], 2-stage preissued -------
// blockIdx.y: 0 -> eH from projT, 1 -> eW from proj
__global__ void gram_f16(const __half* __restrict__ proj, const __half* __restrict__ projT,
                         float* __restrict__ eH, float* __restrict__ eW){
    const __half* P = blockIdx.y ? proj : projT;
    float* E = blockIdx.y ? eW : eH;
    const int bl = blockIdx.x, b = bl >> 7, line = bl & 127;
    const __half* qb = P + (size_t)(b*PROJ_M)*HWc + line*128;
    const __half* kb = qb + (size_t)MID*HWc;

    __shared__ __half Qs[2][32*136];
    __shared__ __half Ks[2][32*136];

    const int tid = threadIdx.x, lane = tid & 31, warp = tid >> 5;
    const int wr = warp >> 1, wc = warp & 1;

    #pragma unroll
    for (int s = 0; s < 2; s++){
        #pragma unroll
        for (int i = 0; i < 2; i++){
            int e = tid + i*256, r = e >> 4, c = e & 15;
            cpa16(sptr(&Qs[s][r*136 + c*8]), qb + (size_t)(s*32+r)*HWc + c*8);
            cpa16(sptr(&Ks[s][r*136 + c*8]), kb + (size_t)(s*32+r)*HWc + c*8);
        }
        CP_COMMIT();
    }

    float acc[2][8][4] = {};

    #pragma unroll
    for (int st = 0; st < 2; st++){
        if (st == 0) { CP_WAIT(1); } else { CP_WAIT(0); }
        __syncthreads();
        const __half* Qc = Qs[st];
        const __half* Kc = Ks[st];
        #pragma unroll
        for (int ks = 0; ks < 2; ks++){
            uint32_t af[2][4], bfm[4][4];
            #pragma unroll
            for (int mt = 0; mt < 2; mt++){
                int row = ks*16 + (lane >> 4)*8 + (lane & 7);      // A via trans
                int col = wr*32 + mt*16 + ((lane >> 3) & 1)*8;
                ldsm4t(af[mt], sptr(Qc + row*136 + col));
            }
            #pragma unroll
            for (int p = 0; p < 4; p++){
                int krow = ks*16 + ((lane >> 3) & 1)*8 + (lane & 7);
                int ncol = wc*64 + p*16 + (lane >> 4)*8;
                ldsm4t(bfm[p], sptr(Kc + krow*136 + ncol));
            }
            #pragma unroll
            for (int mt = 0; mt < 2; mt++)
                #pragma unroll
                for (int nt = 0; nt < 8; nt++)
                    mma_f16(acc[mt][nt], af[mt], bfm[nt>>1][(nt&1)*2], bfm[nt>>1][(nt&1)*2+1]);
        }
    }
    float* eb = E + (size_t)bl*HWc;
    #pragma unroll
    for (int mt = 0; mt < 2; mt++)
        #pragma unroll
        for (int nt = 0; nt < 8; nt++){
            int row = wr*32 + mt*16 + (lane >> 2);
            int col = wc*64 + nt*8 + (lane & 3)*2;
            float2 u0 = { acc[mt][nt][0], acc[mt][nt][1] };
            float2 u1 = { acc[mt][nt][2], acc[mt][nt][3] };
            *(float2*)&eb[(size_t)row*128 + col]     = u0;
            *(float2*)&eb[(size_t)(row+8)*128 + col] = u1;
        }
}

// ---------------- joint softmax, fp32 in -> fp16 probs out --------------------
__global__ void softmax_kernel(const float* __restrict__ eH, const float* __restrict__ eW,
                               __half* __restrict__ aH, __half* __restrict__ aW){
    const int pix  = blockIdx.x*8 + (threadIdx.x >> 5);
    const int lane = threadIdx.x & 31;
    const int w = pix & 127, h = (pix >> 7) & 127, b = pix >> 14;

    const size_t offH = ((size_t)((b*128 + w)*128 + h))*128 + lane*4;
    const size_t offW = ((size_t)((b*128 + h)*128 + w))*128 + lane*4;
    float4 vh = *(const float4*)(eH + offH);
    float4 vw = *(const float4*)(eW + offW);

    const int d = h - lane*4;
    if (d >= 0 && d < 4) ((float*)&vh)[d] = NEGV;

    float mx = fmaxf(fmaxf(fmaxf(vh.x, vh.y), fmaxf(vh.z, vh.w)),
                     fmaxf(fmaxf(vw.x, vw.y), fmaxf(vw.z, vw.w)));
    #pragma unroll
    for (int o = 16; o; o >>= 1) mx = fmaxf(mx, __shfl_xor_sync(0xffffffffu, mx, o));

    vh.x = __expf(vh.x - mx); vh.y = __expf(vh.y - mx);
    vh.z = __expf(vh.z - mx); vh.w = __expf(vh.w - mx);
    vw.x = __expf(vw.x - mx); vw.y = __expf(vw.y - mx);
    vw.z = __expf(vw.z - mx); vw.w = __expf(vw.w - mx);

    float s = vh.x + vh.y + vh.z + vh.w + vw.x + vw.y + vw.z + vw.w;
    #pragma unroll
    for (int o = 16; o; o >>= 1) s += __shfl_xor_sync(0xffffffffu, s, o);
    const float inv = 1.0f / s;

    float4 ph = { vh.x*inv, vh.y*inv, vh.z*inv, vh.w*inv };
    float4 pw = { vw.x*inv, vw.y*inv, vw.z*inv, vw.w*inv };
    *(uint2*)(aH + offH) = f4_to_h4(ph);
    *(uint2*)(aW + offW) = f4_to_h4(pw);
}

// ---------------- apply: Out[c,i] = sum_j V[c,j]*P[i,j], 3-stage async --------
// blockIdx.z: 0 -> (projT, aH) -> oHt ; 1 -> (proj, aW) -> oW
__global__ void apply_f16(const __half* __restrict__ proj, const __half* __restrict__ projT,
                          const __half* __restrict__ aH, const __half* __restrict__ aW,
                          __half* __restrict__ oHt, __half* __restrict__ oW){
    const __half* Vfull = blockIdx.z ? proj : projT;
    const __half* Pm    = blockIdx.z ? aW : aH;
    __half* Outp        = blockIdx.z ? oW : oHt;

    const int bl = blockIdx.y, b = bl >> 7, line = bl & 127;
    const __half* Vb = Vfull + ((size_t)(b*PROJ_M + 128 + blockIdx.x*128))*HWc + line*128;
    const __half* Pb = Pm + (size_t)bl*HWc;
    __half* Ob = Outp + ((size_t)(b*Cch + blockIdx.x*128))*HWc + line*128;

    __shared__ __half Vs[3][128*40];   // [c][j] stride 40
    __shared__ __half Ps[3][128*40];   // [i][j] stride 40

    const int tid = threadIdx.x, lane = tid & 31, warp = tid >> 5;
    const int wr = warp >> 1, wc = warp & 1;

    const __half* vsrc[2]; const __half* psrc[2];
    uint32_t vdst[3][2], pdst[3][2];
    #pragma unroll
    for (int i = 0; i < 2; i++){
        int e = tid + i*256;
        int r = e >> 2, c = e & 3;               // 4 chunks per 32-half row
        vsrc[i] = Vb + (size_t)r*HWc + c*8;
        psrc[i] = Pb + (size_t)r*128 + c*8;
        #pragma unroll
        for (int s = 0; s < 3; s++){
            vdst[s][i] = sptr(&Vs[s][r*40 + c*8]);
            pdst[s][i] = sptr(&Ps[s][r*40 + c*8]);
        }
    }

    float acc[2][8][4] = {};
    const int NIT = 128/32;   // 4

    #pragma unroll
    for (int s = 0; s < 2; s++){
        #pragma unroll
        for (int i = 0; i < 2; i++){
            cpa16(vdst[s][i], vsrc[i] + s*32);
            cpa16(pdst[s][i], psrc[i] + s*32);
        }
        CP_COMMIT();
    }

    for (int it = 0; it < NIT; it++){
        if (it == NIT-1) { CP_WAIT(0); } else { CP_WAIT(1); }
        __syncthreads();
        if (it + 2 < NIT){
            const int s = (it+2) % 3;
            const int j0 = (it+2)*32;
            #pragma unroll
            for (int i = 0; i < 2; i++){
                cpa16(vdst[s][i], vsrc[i] + j0);
                cpa16(pdst[s][i], psrc[i] + j0);
            }
            CP_COMMIT();
        }
        const __half* Vc = Vs[it % 3];
        const __half* Pc = Ps[it % 3];
        #pragma unroll
        for (int ks = 0; ks < 2; ks++){
            uint32_t af[2][4], bfm[4][4];
            #pragma unroll
            for (int mt = 0; mt < 2; mt++){
                int row = wr*32 + mt*16 + (lane & 7) + ((lane >> 3) & 1)*8;
                int col = ks*16 + (lane >> 4)*8;
                ldsm4(af[mt], sptr(Vc + row*40 + col));
            }
            #pragma unroll
            for (int p = 0; p < 4; p++){
                int prow = wc*64 + p*16 + (lane >> 4)*8 + (lane & 7);   // B non-trans
                int pcol = ks*16 + ((lane >> 3) & 1)*8;
                ldsm4(bfm[p], sptr(Pc + prow*40 + pcol));
            }
            #pragma unroll
            for (int mt = 0; mt < 2; mt++)
                #pragma unroll
                for (int nt = 0; nt < 8; nt++)
                    mma_f16(acc[mt][nt], af[mt], bfm[nt>>1][(nt&1)*2], bfm[nt>>1][(nt&1)*2+1]);
        }
    }
    __syncthreads();
    #pragma unroll
    for (int mt = 0; mt < 2; mt++)
        #pragma unroll
        for (int nt = 0; nt < 8; nt++){
            int row = wr*32 + mt*16 + (lane >> 2);
            int col = wc*64 + nt*8 + (lane & 3)*2;
            __half2 u0 = __floats2half2_rn(acc[mt][nt][0], acc[mt][nt][1]);
            __half2 u1 = __floats2half2_rn(acc[mt][nt][2], acc[mt][nt][3]);
            *(__half2*)(Ob + (size_t)row*HWc + col)     = u0;
            *(__half2*)(Ob + (size_t)(row+8)*HWc + col) = u1;
        }
}

// ---------------- combine: out = gamma*(oHt^T + oW) + xh -----------------------
// reads the fp16 copy of x (saves 134MB of fp32 traffic); x is the dominant
// output term so this adds ~1.4e-4 RMS rounding — within budget.
__global__ void combine_kernel(const __half* __restrict__ oHt, const __half* __restrict__ oW,
                               const __half* __restrict__ xh, const float* __restrict__ gamma,
                               float* __restrict__ out){
    __shared__ __half t[64][65];
    const size_t p = blockIdx.z;
    const __half* hp = oHt + p*HWc;
    const int w0 = blockIdx.x*64, h0 = blockIdx.y*64;
    const int tx = threadIdx.x & 15, ty = threadIdx.x >> 4;
    #pragma unroll
    for (int r = 0; r < 64; r += 16){
        uint2 u = *(const uint2*)(hp + (size_t)(w0+ty+r)*128 + h0 + tx*4);
        __half2 lo = *(__half2*)&u.x, hi = *(__half2*)&u.y;
        __half* d = &t[ty+r][tx*4];
        d[0]=lo.x; d[1]=lo.y; d[2]=hi.x; d[3]=hi.y;
    }
    __syncthreads();
    const float g = gamma[0];
    #pragma unroll
    for (int r = 0; r < 64; r += 16){
        const int h = h0 + ty + r;
        const size_t base = p*HWc + (size_t)h*128 + w0 + tx*4;
        uint2 ux = *(const uint2*)(xh + base);
        __half2 xl = *(__half2*)&ux.x, xhh = *(__half2*)&ux.y;
        uint2 uw = *(const uint2*)(oW + base);
        __half2 lo = *(__half2*)&uw.x, hi = *(__half2*)&uw.y;
        float4 o;
        o.x = g*(__half2float(t[tx*4+0][ty+r]) + __half2float(lo.x)) + __half2float(xl.x);
        o.y = g*(__half2float(t[tx*4+1][ty+r]) + __half2float(lo.y)) + __half2float(xl.y);
        o.z = g*(__half2float(t[tx*4+2][ty+r]) + __half2float(hi.x)) + __half2float(xhh.x);
        o.w = g*(__half2float(t[tx*4+3][ty+r]) + __half2float(hi.y)) + __half2float(xhh.y);
        *(float4*)(out + base) = o;
    }
}

// ---------------------------------------------------------------------------
extern "C" void kernel_launch(void* const* d_in, const int* in_sizes, int n_in,
                              void* d_out, int out_size) {
    (void)in_sizes; (void)n_in; (void)out_size;
    const float* x     = (const float*)d_in[0];
    const float* Wq    = (const float*)d_in[1];
    const float* Wk    = (const float*)d_in[2];
    const float* Wv    = (const float*)d_in[3];
    const float* gamma = (const float*)d_in[4];
    float* out = (float*)d_out;

    __half *xh, *wall, *proj, *projT, *aH, *aW, *oHt, *oW;
    float *eH, *eW;
    cudaGetSymbolAddress((void**)&xh,   g_xh);
    cudaGetSymbolAddress((void**)&wall, g_wall);
    cudaGetSymbolAddress((void**)&proj, g_proj);
    cudaGetSymbolAddress((void**)&projT,g_projT);
    cudaGetSymbolAddress((void**)&eH,   g_eH);
    cudaGetSymbolAddress((void**)&eW,   g_eW);
    cudaGetSymbolAddress((void**)&aH,   g_aH);
    cudaGetSymbolAddress((void**)&aW,   g_aW);
    cudaGetSymbolAddress((void**)&oHt,  g_oHt);
    cudaGetSymbolAddress((void**)&oW,   g_oW);

    // 0) fp16 conversion + weight packing
    convert_x<<<(Bsz*Cch*HWc)/(256*4), 256>>>(x, xh);
    pack_w<<<(PROJ_M*Cch)/(256*4), 256>>>(Wq, Wk, Wv, wall);

    // 1) fused projection (q|k|v packed: 640 planes per batch), fp16 HMMA
    proj_f16<<<dim3(HWc/128, PROJ_M/128, Bsz), 256>>>(wall, xh, proj);

    // 2) plane transposes (H<->W for all 640 planes per batch), fp16
    transpose_f16<<<dim3(2,2,Bsz*PROJ_M), 256>>>(proj, projT);

    // 3) attention scores (y=0: eH from projT, y=1: eW from proj), fp32 out
    gram_f16<<<dim3(Bsz*128, 2), 256>>>(proj, projT, eH, eW);

    // 4) joint softmax -> fp16 probs
    softmax_kernel<<<(Bsz*HWc)/8, 256>>>(eH, eW, aH, aW);

    // 5) apply attention (z=0 -> oHt, z=1 -> oW), fp16 out
    apply_f16<<<dim3(Cch/128, Bsz*128, 2), 256>>>(proj, projT, aH, aW, oHt, oW);

    // 6) combine (reads fp16 xh)
    combine_kernel<<<dim3(2,2,Bsz*Cch), 256>>>(oHt, oW, xh, gamma, out);
}

// round 13
// speedup vs baseline: 1.1079x; 1.0155x over previous
#include <cuda_runtime.h>
#include <cuda_fp16.h>
#include <cstdint>

#define Bsz 4
#define Cch 512
#define MID 64
#define HWc 16384
#define PROJ_M 640
#define NEGV (-60000.0f)

// ---------------- scratch ----------------------------------------------------
__device__ __align__(16) __half g_xh  [(size_t)Bsz*Cch*HWc];
__device__ __align__(16) __half g_wall[PROJ_M*Cch];
__device__ __align__(16) __half g_proj [(size_t)Bsz*PROJ_M*HWc];
__device__ __align__(16) __half g_projT[(size_t)Bsz*PROJ_M*HWc];
__device__ __align__(16) __half g_eH[(size_t)Bsz*128*HWc];   // fp16 logits -> probs (in place)
__device__ __align__(16) __half g_eW[(size_t)Bsz*128*HWc];
__device__ __align__(16) __half g_oHt[(size_t)Bsz*Cch*HWc];
__device__ __align__(16) __half g_oW [(size_t)Bsz*Cch*HWc];

// ---------------- helpers ------------------------------------------------------
__device__ __forceinline__ uint32_t sptr(const void* p){
    return (uint32_t)__cvta_generic_to_shared(p);
}
__device__ __forceinline__ void cpa16(uint32_t s, const void* g){
    asm volatile("cp.async.ca.shared.global [%0], [%1], 16;" :: "r"(s), "l"(g));
}
#define CP_COMMIT() asm volatile("cp.async.commit_group;")
#define CP_WAIT(n)  asm volatile("cp.async.wait_group %0;" :: "n"(n))

__device__ __forceinline__ void ldsm4(uint32_t* r, uint32_t a){
    asm volatile("ldmatrix.sync.aligned.m8n8.x4.shared.b16 {%0,%1,%2,%3},[%4];"
        : "=r"(r[0]),"=r"(r[1]),"=r"(r[2]),"=r"(r[3]) : "r"(a));
}
__device__ __forceinline__ void ldsm4t(uint32_t* r, uint32_t a){
    asm volatile("ldmatrix.sync.aligned.m8n8.x4.trans.shared.b16 {%0,%1,%2,%3},[%4];"
        : "=r"(r[0]),"=r"(r[1]),"=r"(r[2]),"=r"(r[3]) : "r"(a));
}
__device__ __forceinline__ void mma_f16(float* c, const uint32_t* a, uint32_t b0, uint32_t b1){
    asm volatile(
        "mma.sync.aligned.m16n8k16.row.col.f32.f16.f16.f32 "
        "{%0,%1,%2,%3}, {%4,%5,%6,%7}, {%8,%9}, {%0,%1,%2,%3};"
        : "+f"(c[0]),"+f"(c[1]),"+f"(c[2]),"+f"(c[3])
        : "r"(a[0]),"r"(a[1]),"r"(a[2]),"r"(a[3]),"r"(b0),"r"(b1));
}
__device__ __forceinline__ uint2 f4_to_h4(float4 v){
    __half2 a = __floats2half2_rn(v.x, v.y);
    __half2 b = __floats2half2_rn(v.z, v.w);
    uint2 u; u.x = *(uint32_t*)&a; u.y = *(uint32_t*)&b; return u;
}

// ---------------- conversions --------------------------------------------------
__global__ void convert_x(const float* __restrict__ x, __half* __restrict__ xh){
    size_t i = ((size_t)blockIdx.x*256 + threadIdx.x)*4;
    *(uint2*)(xh + i) = f4_to_h4(*(const float4*)(x + i));
}
__global__ void pack_w(const float* __restrict__ Wq, const float* __restrict__ Wk,
                       const float* __restrict__ Wv, __half* __restrict__ wall){
    int i = (blockIdx.x*256 + threadIdx.x)*4;
    int row = i >> 9, col = i & 511;
    const float* src = row < 64 ? Wq + (size_t)row*512
                     : row < 128 ? Wk + (size_t)(row-64)*512
                                 : Wv + (size_t)(row-128)*512;
    *(uint2*)(wall + i) = f4_to_h4(*(const float4*)(src + col));
}

// ---------------- projection: proj[b] = Wall(640x512) @ xh[b](512x16384) -----
// block 128m x 128n, BK=32, 3-stage cp.async; 8 warps (4x2), warp tile 32x64.
__global__ void proj_f16(const __half* __restrict__ Wall, const __half* __restrict__ xh,
                         __half* __restrict__ Out){
    const int b = blockIdx.z;
    const int m0blk = blockIdx.y * 128;
    const __half* Bg = xh + (size_t)b*Cch*HWc + blockIdx.x*128;
    __half* Cg = Out + ((size_t)b*PROJ_M + m0blk)*HWc + blockIdx.x*128;

    __shared__ __half As[3][128*40];   // [m][k] stride 40
    __shared__ __half Bs[3][32*136];   // [k][n] stride 136

    const int tid = threadIdx.x, lane = tid & 31, warp = tid >> 5;
    const int wr = warp >> 1, wc = warp & 1;

    const __half* asrc[2]; const __half* bsrc[2];
    uint32_t adst[3][2], bdst[3][2];
    #pragma unroll
    for (int i = 0; i < 2; i++){
        int e = tid + i*256;
        int ra = e >> 2, ca = e & 3;               // A: 4 chunks per 32-half row
        asrc[i] = Wall + (size_t)(m0blk + ra)*Cch + ca*8;
        int rb = e >> 4, cb = e & 15;              // B: 16 chunks per 128-half row
        bsrc[i] = Bg + (size_t)rb*HWc + cb*8;
        #pragma unroll
        for (int s = 0; s < 3; s++){
            adst[s][i] = sptr(&As[s][ra*40 + ca*8]);
            bdst[s][i] = sptr(&Bs[s][rb*136 + cb*8]);
        }
    }

    float acc[2][8][4] = {};
    const int NIT = Cch/32;   // 16

    #pragma unroll
    for (int s = 0; s < 2; s++){
        const int k0 = s*32;
        #pragma unroll
        for (int i = 0; i < 2; i++){
            cpa16(adst[s][i], asrc[i] + k0);
            cpa16(bdst[s][i], bsrc[i] + (size_t)k0*HWc);
        }
        CP_COMMIT();
    }

    for (int it = 0; it < NIT; it++){
        if (it == NIT-1) { CP_WAIT(0); } else { CP_WAIT(1); }
        __syncthreads();
        if (it + 2 < NIT){
            const int s = (it+2) % 3;
            const int k0 = (it+2)*32;
            #pragma unroll
            for (int i = 0; i < 2; i++){
                cpa16(adst[s][i], asrc[i] + k0);
                cpa16(bdst[s][i], bsrc[i] + (size_t)k0*HWc);
            }
            CP_COMMIT();
        }
        const __half* Ac = As[it % 3];
        const __half* Bc = Bs[it % 3];
        #pragma unroll
        for (int ks = 0; ks < 2; ks++){
            uint32_t af[2][4], bfm[4][4];
            #pragma unroll
            for (int mt = 0; mt < 2; mt++){
                int row = wr*32 + mt*16 + (lane & 7) + ((lane >> 3) & 1)*8;
                int col = ks*16 + (lane >> 4)*8;
                ldsm4(af[mt], sptr(Ac + row*40 + col));
            }
            #pragma unroll
            for (int p = 0; p < 4; p++){
                int krow = ks*16 + ((lane >> 3) & 1)*8 + (lane & 7);
                int ncol = wc*64 + p*16 + (lane >> 4)*8;
                ldsm4t(bfm[p], sptr(Bc + krow*136 + ncol));
            }
            #pragma unroll
            for (int mt = 0; mt < 2; mt++)
                #pragma unroll
                for (int nt = 0; nt < 8; nt++)
                    mma_f16(acc[mt][nt], af[mt], bfm[nt>>1][(nt&1)*2], bfm[nt>>1][(nt&1)*2+1]);
        }
    }
    __syncthreads();
    #pragma unroll
    for (int mt = 0; mt < 2; mt++)
        #pragma unroll
        for (int nt = 0; nt < 8; nt++){
            int row = wr*32 + mt*16 + (lane >> 2);
            int col = wc*64 + nt*8 + (lane & 3)*2;
            __half2 u0 = __floats2half2_rn(acc[mt][nt][0], acc[mt][nt][1]);
            __half2 u1 = __floats2half2_rn(acc[mt][nt][2], acc[mt][nt][3]);
            *(__half2*)(Cg + (size_t)row*HWc + col)     = u0;
            *(__half2*)(Cg + (size_t)(row+8)*HWc + col) = u1;
        }
}

// ---------------- 128x128 fp16 plane transpose (64x64 tiles) ------------------
__global__ void transpose_f16(const __half* __restrict__ in, __half* __restrict__ out){
    __shared__ __half t[64][65];
    const size_t p = blockIdx.z;
    const __half* ip = in + p*HWc;
    __half* op = out + p*HWc;
    const int x0 = blockIdx.x*64, y0 = blockIdx.y*64;
    const int tx = threadIdx.x & 15, ty = threadIdx.x >> 4;
    #pragma unroll
    for (int r = 0; r < 64; r += 16){
        uint2 u = *(const uint2*)(ip + (size_t)(y0+ty+r)*128 + x0 + tx*4);
        __half2 lo = *(__half2*)&u.x, hi = *(__half2*)&u.y;
        __half* d = &t[ty+r][tx*4];
        d[0]=lo.x; d[1]=lo.y; d[2]=hi.x; d[3]=hi.y;
    }
    __syncthreads();
    #pragma unroll
    for (int r = 0; r < 64; r += 16){
        __half2 lo, hi;
        lo.x = t[tx*4+0][ty+r]; lo.y = t[tx*4+1][ty+r];
        hi.x = t[tx*4+2][ty+r]; hi.y = t[tx*4+3][ty+r];
        uint2 u; u.x = *(uint32_t*)&lo; u.y = *(uint32_t*)&hi;
        *(uint2*)(op + (size_t)(x0+ty+r)*128 + y0 + tx*4) = u;
    }
}

// ---------------- gram: E[i,j] = sum_m Q[m,i]*K[m,j] -> fp16 logits -----------
// blockIdx.y: 0 -> eH from projT, 1 -> eW from proj
__global__ void gram_f16(const __half* __restrict__ proj, const __half* __restrict__ projT,
                         __half* __restrict__ eH, __half* __restrict__ eW){
    const __half* P = blockIdx.y ? proj : projT;
    __half* E = blockIdx.y ? eW : eH;
    const int bl = blockIdx.x, b = bl >> 7, line = bl & 127;
    const __half* qb = P + (size_t)(b*PROJ_M)*HWc + line*128;
    const __half* kb = qb + (size_t)MID*HWc;

    __shared__ __half Qs[2][32*136];
    __shared__ __half Ks[2][32*136];

    const int tid = threadIdx.x, lane = tid & 31, warp = tid >> 5;
    const int wr = warp >> 1, wc = warp & 1;

    #pragma unroll
    for (int s = 0; s < 2; s++){
        #pragma unroll
        for (int i = 0; i < 2; i++){
            int e = tid + i*256, r = e >> 4, c = e & 15;
            cpa16(sptr(&Qs[s][r*136 + c*8]), qb + (size_t)(s*32+r)*HWc + c*8);
            cpa16(sptr(&Ks[s][r*136 + c*8]), kb + (size_t)(s*32+r)*HWc + c*8);
        }
        CP_COMMIT();
    }

    float acc[2][8][4] = {};

    #pragma unroll
    for (int st = 0; st < 2; st++){
        if (st == 0) { CP_WAIT(1); } else { CP_WAIT(0); }
        __syncthreads();
        const __half* Qc = Qs[st];
        const __half* Kc = Ks[st];
        #pragma unroll
        for (int ks = 0; ks < 2; ks++){
            uint32_t af[2][4], bfm[4][4];
            #pragma unroll
            for (int mt = 0; mt < 2; mt++){
                int row = ks*16 + (lane >> 4)*8 + (lane & 7);      // A via trans
                int col = wr*32 + mt*16 + ((lane >> 3) & 1)*8;
                ldsm4t(af[mt], sptr(Qc + row*136 + col));
            }
            #pragma unroll
            for (int p = 0; p < 4; p++){
                int krow = ks*16 + ((lane >> 3) & 1)*8 + (lane & 7);
                int ncol = wc*64 + p*16 + (lane >> 4)*8;
                ldsm4t(bfm[p], sptr(Kc + krow*136 + ncol));
            }
            #pragma unroll
            for (int mt = 0; mt < 2; mt++)
                #pragma unroll
                for (int nt = 0; nt < 8; nt++)
                    mma_f16(acc[mt][nt], af[mt], bfm[nt>>1][(nt&1)*2], bfm[nt>>1][(nt&1)*2+1]);
        }
    }
    __half* eb = E + (size_t)bl*HWc;
    #pragma unroll
    for (int mt = 0; mt < 2; mt++)
        #pragma unroll
        for (int nt = 0; nt < 8; nt++){
            int row = wr*32 + mt*16 + (lane >> 2);
            int col = wc*64 + nt*8 + (lane & 3)*2;
            __half2 u0 = __floats2half2_rn(acc[mt][nt][0], acc[mt][nt][1]);
            __half2 u1 = __floats2half2_rn(acc[mt][nt][2], acc[mt][nt][3]);
            *(__half2*)&eb[(size_t)row*128 + col]     = u0;
            *(__half2*)&eb[(size_t)(row+8)*128 + col] = u1;
        }
}

// ---------------- joint softmax: fp16 logits in -> fp16 probs out (in place) --
__global__ void softmax_kernel(__half* __restrict__ eH, __half* __restrict__ eW){
    const int pix  = blockIdx.x*8 + (threadIdx.x >> 5);
    const int lane = threadIdx.x & 31;
    const int w = pix & 127, h = (pix >> 7) & 127, b = pix >> 14;

    const size_t offH = ((size_t)((b*128 + w)*128 + h))*128 + lane*4;
    const size_t offW = ((size_t)((b*128 + h)*128 + w))*128 + lane*4;
    uint2 uh = *(const uint2*)(eH + offH);
    uint2 uw = *(const uint2*)(eW + offW);
    __half2 h0 = *(__half2*)&uh.x, h1 = *(__half2*)&uh.y;
    __half2 w0 = *(__half2*)&uw.x, w1 = *(__half2*)&uw.y;
    float4 vh = { __half2float(h0.x), __half2float(h0.y),
                  __half2float(h1.x), __half2float(h1.y) };
    float4 vw = { __half2float(w0.x), __half2float(w0.y),
                  __half2float(w1.x), __half2float(w1.y) };

    const int d = h - lane*4;
    if (d >= 0 && d < 4) ((float*)&vh)[d] = NEGV;

    float mx = fmaxf(fmaxf(fmaxf(vh.x, vh.y), fmaxf(vh.z, vh.w)),
                     fmaxf(fmaxf(vw.x, vw.y), fmaxf(vw.z, vw.w)));
    #pragma unroll
    for (int o = 16; o; o >>= 1) mx = fmaxf(mx, __shfl_xor_sync(0xffffffffu, mx, o));

    vh.x = __expf(vh.x - mx); vh.y = __expf(vh.y - mx);
    vh.z = __expf(vh.z - mx); vh.w = __expf(vh.w - mx);
    vw.x = __expf(vw.x - mx); vw.y = __expf(vw.y - mx);
    vw.z = __expf(vw.z - mx); vw.w = __expf(vw.w - mx);

    float s = vh.x + vh.y + vh.z + vh.w + vw.x + vw.y + vw.z + vw.w;
    #pragma unroll
    for (int o = 16; o; o >>= 1) s += __shfl_xor_sync(0xffffffffu, s, o);
    const float inv = 1.0f / s;

    float4 ph = { vh.x*inv, vh.y*inv, vh.z*inv, vh.w*inv };
    float4 pw = { vw.x*inv, vw.y*inv, vw.z*inv, vw.w*inv };
    *(uint2*)(eH + offH) = f4_to_h4(ph);
    *(uint2*)(eW + offW) = f4_to_h4(pw);
}

// ---------------- apply: Out[c,i] = sum_j V[c,j]*P[i,j], 3-stage async --------
// blockIdx.z: 0 -> (projT, eH-probs) -> oHt ; 1 -> (proj, eW-probs) -> oW
__global__ void apply_f16(const __half* __restrict__ proj, const __half* __restrict__ projT,
                          const __half* __restrict__ aH, const __half* __restrict__ aW,
                          __half* __restrict__ oHt, __half* __restrict__ oW){
    const __half* Vfull = blockIdx.z ? proj : projT;
    const __half* Pm    = blockIdx.z ? aW : aH;
    __half* Outp        = blockIdx.z ? oW : oHt;

    const int bl = blockIdx.y, b = bl >> 7, line = bl & 127;
    const __half* Vb = Vfull + ((size_t)(b*PROJ_M + 128 + blockIdx.x*128))*HWc + line*128;
    const __half* Pb = Pm + (size_t)bl*HWc;
    __half* Ob = Outp + ((size_t)(b*Cch + blockIdx.x*128))*HWc + line*128;

    __shared__ __half Vs[3][128*40];   // [c][j] stride 40
    __shared__ __half Ps[3][128*40];   // [i][j] stride 40

    const int tid = threadIdx.x, lane = tid & 31, warp = tid >> 5;
    const int wr = warp >> 1, wc = warp & 1;

    const __half* vsrc[2]; const __half* psrc[2];
    uint32_t vdst[3][2], pdst[3][2];
    #pragma unroll
    for (int i = 0; i < 2; i++){
        int e = tid + i*256;
        int r = e >> 2, c = e & 3;               // 4 chunks per 32-half row
        vsrc[i] = Vb + (size_t)r*HWc + c*8;
        psrc[i] = Pb + (size_t)r*128 + c*8;
        #pragma unroll
        for (int s = 0; s < 3; s++){
            vdst[s][i] = sptr(&Vs[s][r*40 + c*8]);
            pdst[s][i] = sptr(&Ps[s][r*40 + c*8]);
        }
    }

    float acc[2][8][4] = {};
    const int NIT = 128/32;   // 4

    #pragma unroll
    for (int s = 0; s < 2; s++){
        #pragma unroll
        for (int i = 0; i < 2; i++){
            cpa16(vdst[s][i], vsrc[i] + s*32);
            cpa16(pdst[s][i], psrc[i] + s*32);
        }
        CP_COMMIT();
    }

    for (int it = 0; it < NIT; it++){
        if (it == NIT-1) { CP_WAIT(0); } else { CP_WAIT(1); }
        __syncthreads();
        if (it + 2 < NIT){
            const int s = (it+2) % 3;
            const int j0 = (it+2)*32;
            #pragma unroll
            for (int i = 0; i < 2; i++){
                cpa16(vdst[s][i], vsrc[i] + j0);
                cpa16(pdst[s][i], psrc[i] + j0);
            }
            CP_COMMIT();
        }
        const __half* Vc = Vs[it % 3];
        const __half* Pc = Ps[it % 3];
        #pragma unroll
        for (int ks = 0; ks < 2; ks++){
            uint32_t af[2][4], bfm[4][4];
            #pragma unroll
            for (int mt = 0; mt < 2; mt++){
                int row = wr*32 + mt*16 + (lane & 7) + ((lane >> 3) & 1)*8;
                int col = ks*16 + (lane >> 4)*8;
                ldsm4(af[mt], sptr(Vc + row*40 + col));
            }
            #pragma unroll
            for (int p = 0; p < 4; p++){
                int prow = wc*64 + p*16 + (lane >> 4)*8 + (lane & 7);   // B non-trans
                int pcol = ks*16 + ((lane >> 3) & 1)*8;
                ldsm4(bfm[p], sptr(Pc + prow*40 + pcol));
            }
            #pragma unroll
            for (int mt = 0; mt < 2; mt++)
                #pragma unroll
                for (int nt = 0; nt < 8; nt++)
                    mma_f16(acc[mt][nt], af[mt], bfm[nt>>1][(nt&1)*2], bfm[nt>>1][(nt&1)*2+1]);
        }
    }
    __syncthreads();
    #pragma unroll
    for (int mt = 0; mt < 2; mt++)
        #pragma unroll
        for (int nt = 0; nt < 8; nt++){
            int row = wr*32 + mt*16 + (lane >> 2);
            int col = wc*64 + nt*8 + (lane & 3)*2;
            __half2 u0 = __floats2half2_rn(acc[mt][nt][0], acc[mt][nt][1]);
            __half2 u1 = __floats2half2_rn(acc[mt][nt][2], acc[mt][nt][3]);
            *(__half2*)(Ob + (size_t)row*HWc + col)     = u0;
            *(__half2*)(Ob + (size_t)(row+8)*HWc + col) = u1;
        }
}

// ---------------- combine: out = gamma*(oHt^T + oW) + xh -----------------------
__global__ void combine_kernel(const __half* __restrict__ oHt, const __half* __restrict__ oW,
                               const __half* __restrict__ xh, const float* __restrict__ gamma,
                               float* __restrict__ out){
    __shared__ __half t[64][65];
    const size_t p = blockIdx.z;
    const __half* hp = oHt + p*HWc;
    const int w0 = blockIdx.x*64, h0 = blockIdx.y*64;
    const int tx = threadIdx.x & 15, ty = threadIdx.x >> 4;
    #pragma unroll
    for (int r = 0; r < 64; r += 16){
        uint2 u = *(const uint2*)(hp + (size_t)(w0+ty+r)*128 + h0 + tx*4);
        __half2 lo = *(__half2*)&u.x, hi = *(__half2*)&u.y;
        __half* d = &t[ty+r][tx*4];
        d[0]=lo.x; d[1]=lo.y; d[2]=hi.x; d[3]=hi.y;
    }
    __syncthreads();
    const float g = gamma[0];
    #pragma unroll
    for (int r = 0; r < 64; r += 16){
        const int h = h0 + ty + r;
        const size_t base = p*HWc + (size_t)h*128 + w0 + tx*4;
        uint2 ux = *(const uint2*)(xh + base);
        __half2 xl = *(__half2*)&ux.x, xhh = *(__half2*)&ux.y;
        uint2 uw = *(const uint2*)(oW + base);
        __half2 lo = *(__half2*)&uw.x, hi = *(__half2*)&uw.y;
        float4 o;
        o.x = g*(__half2float(t[tx*4+0][ty+r]) + __half2float(lo.x)) + __half2float(xl.x);
        o.y = g*(__half2float(t[tx*4+1][ty+r]) + __half2float(lo.y)) + __half2float(xl.y);
        o.z = g*(__half2float(t[tx*4+2][ty+r]) + __half2float(hi.x)) + __half2float(xhh.x);
        o.w = g*(__half2float(t[tx*4+3][ty+r]) + __half2float(hi.y)) + __half2float(xhh.y);
        *(float4*)(out + base) = o;
    }
}

// ---------------------------------------------------------------------------
extern "C" void kernel_launch(void* const* d_in, const int* in_sizes, int n_in,
                              void* d_out, int out_size) {
    (void)in_sizes; (void)n_in; (void)out_size;
    const float* x     = (const float*)d_in[0];
    const float* Wq    = (const float*)d_in[1];
    const float* Wk    = (const float*)d_in[2];
    const float* Wv    = (const float*)d_in[3];
    const float* gamma = (const float*)d_in[4];
    float* out = (float*)d_out;

    __half *xh, *wall, *proj, *projT, *eH, *eW, *oHt, *oW;
    cudaGetSymbolAddress((void**)&xh,   g_xh);
    cudaGetSymbolAddress((void**)&wall, g_wall);
    cudaGetSymbolAddress((void**)&proj, g_proj);
    cudaGetSymbolAddress((void**)&projT,g_projT);
    cudaGetSymbolAddress((void**)&eH,   g_eH);
    cudaGetSymbolAddress((void**)&eW,   g_eW);
    cudaGetSymbolAddress((void**)&oHt,  g_oHt);
    cudaGetSymbolAddress((void**)&oW,   g_oW);

    // 0) fp16 conversion + weight packing
    convert_x<<<(Bsz*Cch*HWc)/(256*4), 256>>>(x, xh);
    pack_w<<<(PROJ_M*Cch)/(256*4), 256>>>(Wq, Wk, Wv, wall);

    // 1) fused projection (q|k|v packed: 640 planes per batch), fp16 HMMA
    proj_f16<<<dim3(HWc/128, PROJ_M/128, Bsz), 256>>>(wall, xh, proj);

    // 2) plane transposes (H<->W for all 640 planes per batch), fp16
    transpose_f16<<<dim3(2,2,Bsz*PROJ_M), 256>>>(proj, projT);

    // 3) attention scores -> fp16 logits (128MB total: L2-resident chain)
    gram_f16<<<dim3(Bsz*128, 2), 256>>>(proj, projT, eH, eW);

    // 4) joint softmax in place: fp16 logits -> fp16 probs
    softmax_kernel<<<(Bsz*HWc)/8, 256>>>(eH, eW);

    // 5) apply attention (z=0 -> oHt, z=1 -> oW), fp16 out
    apply_f16<<<dim3(Cch/128, Bsz*128, 2), 256>>>(proj, projT, eH, eW, oHt, oW);

    // 6) combine (reads fp16 xh)
    combine_kernel<<<dim3(2,2,Bsz*Cch), 256>>>(oHt, oW, xh, gamma, out);
}

// round 14
// speedup vs baseline: 1.1651x; 1.0516x over previous
#include <cuda_runtime.h>
#include <cuda_fp16.h>
#include <cstdint>

#define Bsz 4
#define Cch 512
#define MID 64
#define HWc 16384
#define PROJ_M 640
#define NEGV (-60000.0f)

// ---------------- scratch ----------------------------------------------------
__device__ __align__(16) __half g_xh  [(size_t)Bsz*Cch*HWc];
__device__ __align__(16) __half g_wall[PROJ_M*Cch];
__device__ __align__(16) __half g_proj [(size_t)Bsz*PROJ_M*HWc];
__device__ __align__(16) __half g_projT[(size_t)Bsz*PROJ_M*HWc];
__device__ __align__(16) __half g_eH[(size_t)Bsz*128*HWc];   // fp16 logits -> probs (in place)
__device__ __align__(16) __half g_eW[(size_t)Bsz*128*HWc];
__device__ __align__(16) __half g_oHt[(size_t)Bsz*Cch*HWc];
__device__ __align__(16) __half g_oW [(size_t)Bsz*Cch*HWc];

// ---------------- helpers ------------------------------------------------------
__device__ __forceinline__ uint32_t sptr(const void* p){
    return (uint32_t)__cvta_generic_to_shared(p);
}
__device__ __forceinline__ void cpa16(uint32_t s, const void* g){
    asm volatile("cp.async.ca.shared.global [%0], [%1], 16;" :: "r"(s), "l"(g));
}
#define CP_COMMIT() asm volatile("cp.async.commit_group;")
#define CP_WAIT(n)  asm volatile("cp.async.wait_group %0;" :: "n"(n))

__device__ __forceinline__ void ldsm4(uint32_t* r, uint32_t a){
    asm volatile("ldmatrix.sync.aligned.m8n8.x4.shared.b16 {%0,%1,%2,%3},[%4];"
        : "=r"(r[0]),"=r"(r[1]),"=r"(r[2]),"=r"(r[3]) : "r"(a));
}
__device__ __forceinline__ void ldsm4t(uint32_t* r, uint32_t a){
    asm volatile("ldmatrix.sync.aligned.m8n8.x4.trans.shared.b16 {%0,%1,%2,%3},[%4];"
        : "=r"(r[0]),"=r"(r[1]),"=r"(r[2]),"=r"(r[3]) : "r"(a));
}
__device__ __forceinline__ void mma_f16(float* c, const uint32_t* a, uint32_t b0, uint32_t b1){
    asm volatile(
        "mma.sync.aligned.m16n8k16.row.col.f32.f16.f16.f32 "
        "{%0,%1,%2,%3}, {%4,%5,%6,%7}, {%8,%9}, {%0,%1,%2,%3};"
        : "+f"(c[0]),"+f"(c[1]),"+f"(c[2]),"+f"(c[3])
        : "r"(a[0]),"r"(a[1]),"r"(a[2]),"r"(a[3]),"r"(b0),"r"(b1));
}
__device__ __forceinline__ uint2 f4_to_h4(float4 v){
    __half2 a = __floats2half2_rn(v.x, v.y);
    __half2 b = __floats2half2_rn(v.z, v.w);
    uint2 u; u.x = *(uint32_t*)&a; u.y = *(uint32_t*)&b; return u;
}

// ---------------- conversion + weight pack, single launch ----------------------
#define CONV_BLOCKS ((Bsz*Cch*HWc)/(256*4))      // 32768
__global__ void convert_all(const float* __restrict__ x, __half* __restrict__ xh,
                            const float* __restrict__ Wq, const float* __restrict__ Wk,
                            const float* __restrict__ Wv, __half* __restrict__ wall){
    if (blockIdx.x < CONV_BLOCKS){
        size_t i = ((size_t)blockIdx.x*256 + threadIdx.x)*4;
        *(uint2*)(xh + i) = f4_to_h4(*(const float4*)(x + i));
    } else {
        int i = ((blockIdx.x - CONV_BLOCKS)*256 + threadIdx.x)*4;
        int row = i >> 9, col = i & 511;
        const float* src = row < 64 ? Wq + (size_t)row*512
                         : row < 128 ? Wk + (size_t)(row-64)*512
                                     : Wv + (size_t)(row-128)*512;
        *(uint2*)(wall + i) = f4_to_h4(*(const float4*)(src + col));
    }
}

// ---------------- projection: proj[b] = Wall(640x512) @ xh[b](512x16384) -----
// block 128m x 128n, BK=32, 2-stage cp.async (38KB smem, 2 blocks/SM target);
// 8 warps (4x2), warp tile 32x64. Safe ordering: compute -> sync -> reissue.
__global__ void __launch_bounds__(256, 2) proj_f16(
        const __half* __restrict__ Wall, const __half* __restrict__ xh,
        __half* __restrict__ Out){
    const int b = blockIdx.z;
    const int m0blk = blockIdx.y * 128;
    const __half* Bg = xh + (size_t)b*Cch*HWc + blockIdx.x*128;
    __half* Cg = Out + ((size_t)b*PROJ_M + m0blk)*HWc + blockIdx.x*128;

    __shared__ __half As[2][128*40];   // [m][k] stride 40
    __shared__ __half Bs[2][32*136];   // [k][n] stride 136

    const int tid = threadIdx.x, lane = tid & 31, warp = tid >> 5;
    const int wr = warp >> 1, wc = warp & 1;

    const __half* asrc[2]; const __half* bsrc[2];
    uint32_t adst[2][2], bdst[2][2];
    #pragma unroll
    for (int i = 0; i < 2; i++){
        int e = tid + i*256;
        int ra = e >> 2, ca = e & 3;               // A: 4 chunks per 32-half row
        asrc[i] = Wall + (size_t)(m0blk + ra)*Cch + ca*8;
        int rb = e >> 4, cb = e & 15;              // B: 16 chunks per 128-half row
        bsrc[i] = Bg + (size_t)rb*HWc + cb*8;
        #pragma unroll
        for (int s = 0; s < 2; s++){
            adst[s][i] = sptr(&As[s][ra*40 + ca*8]);
            bdst[s][i] = sptr(&Bs[s][rb*136 + cb*8]);
        }
    }

    float acc[2][8][4] = {};
    const int NIT = Cch/32;   // 16

    #pragma unroll
    for (int s = 0; s < 2; s++){
        const int k0 = s*32;
        #pragma unroll
        for (int i = 0; i < 2; i++){
            cpa16(adst[s][i], asrc[i] + k0);
            cpa16(bdst[s][i], bsrc[i] + (size_t)k0*HWc);
        }
        CP_COMMIT();
    }

    for (int it = 0; it < NIT; it++){
        if (it == NIT-1) { CP_WAIT(0); } else { CP_WAIT(1); }
        __syncthreads();
        const int cur = it & 1;
        const __half* Ac = As[cur];
        const __half* Bc = Bs[cur];
        #pragma unroll
        for (int ks = 0; ks < 2; ks++){
            uint32_t af[2][4], bfm[4][4];
            #pragma unroll
            for (int mt = 0; mt < 2; mt++){
                int row = wr*32 + mt*16 + (lane & 7) + ((lane >> 3) & 1)*8;
                int col = ks*16 + (lane >> 4)*8;
                ldsm4(af[mt], sptr(Ac + row*40 + col));
            }
            #pragma unroll
            for (int p = 0; p < 4; p++){
                int krow = ks*16 + ((lane >> 3) & 1)*8 + (lane & 7);
                int ncol = wc*64 + p*16 + (lane >> 4)*8;
                ldsm4t(bfm[p], sptr(Bc + krow*136 + ncol));
            }
            #pragma unroll
            for (int mt = 0; mt < 2; mt++)
                #pragma unroll
                for (int nt = 0; nt < 8; nt++)
                    mma_f16(acc[mt][nt], af[mt], bfm[nt>>1][(nt&1)*2], bfm[nt>>1][(nt&1)*2+1]);
        }
        __syncthreads();                 // all warps done reading cur
        if (it + 2 < NIT){               // refill cur for iteration it+2
            const int k0 = (it+2)*32;
            #pragma unroll
            for (int i = 0; i < 2; i++){
                cpa16(adst[cur][i], asrc[i] + k0);
                cpa16(bdst[cur][i], bsrc[i] + (size_t)k0*HWc);
            }
            CP_COMMIT();
        }
    }
    #pragma unroll
    for (int mt = 0; mt < 2; mt++)
        #pragma unroll
        for (int nt = 0; nt < 8; nt++){
            int row = wr*32 + mt*16 + (lane >> 2);
            int col = wc*64 + nt*8 + (lane & 3)*2;
            __half2 u0 = __floats2half2_rn(acc[mt][nt][0], acc[mt][nt][1]);
            __half2 u1 = __floats2half2_rn(acc[mt][nt][2], acc[mt][nt][3]);
            *(__half2*)(Cg + (size_t)row*HWc + col)     = u0;
            *(__half2*)(Cg + (size_t)(row+8)*HWc + col) = u1;
        }
}

// ---------------- 128x128 fp16 plane transpose (64x64 tiles) ------------------
__global__ void transpose_f16(const __half* __restrict__ in, __half* __restrict__ out){
    __shared__ __half t[64][65];
    const size_t p = blockIdx.z;
    const __half* ip = in + p*HWc;
    __half* op = out + p*HWc;
    const int x0 = blockIdx.x*64, y0 = blockIdx.y*64;
    const int tx = threadIdx.x & 15, ty = threadIdx.x >> 4;
    #pragma unroll
    for (int r = 0; r < 64; r += 16){
        uint2 u = *(const uint2*)(ip + (size_t)(y0+ty+r)*128 + x0 + tx*4);
        __half2 lo = *(__half2*)&u.x, hi = *(__half2*)&u.y;
        __half* d = &t[ty+r][tx*4];
        d[0]=lo.x; d[1]=lo.y; d[2]=hi.x; d[3]=hi.y;
    }
    __syncthreads();
    #pragma unroll
    for (int r = 0; r < 64; r += 16){
        __half2 lo, hi;
        lo.x = t[tx*4+0][ty+r]; lo.y = t[tx*4+1][ty+r];
        hi.x = t[tx*4+2][ty+r]; hi.y = t[tx*4+3][ty+r];
        uint2 u; u.x = *(uint32_t*)&lo; u.y = *(uint32_t*)&hi;
        *(uint2*)(op + (size_t)(x0+ty+r)*128 + y0 + tx*4) = u;
    }
}

// ---------------- gram: E[i,j] = sum_m Q[m,i]*K[m,j] -> fp16 logits -----------
// blockIdx.y: 0 -> eH from projT, 1 -> eW from proj
__global__ void gram_f16(const __half* __restrict__ proj, const __half* __restrict__ projT,
                         __half* __restrict__ eH, __half* __restrict__ eW){
    const __half* P = blockIdx.y ? proj : projT;
    __half* E = blockIdx.y ? eW : eH;
    const int bl = blockIdx.x, b = bl >> 7, line = bl & 127;
    const __half* qb = P + (size_t)(b*PROJ_M)*HWc + line*128;
    const __half* kb = qb + (size_t)MID*HWc;

    __shared__ __half Qs[2][32*136];
    __shared__ __half Ks[2][32*136];

    const int tid = threadIdx.x, lane = tid & 31, warp = tid >> 5;
    const int wr = warp >> 1, wc = warp & 1;

    #pragma unroll
    for (int s = 0; s < 2; s++){
        #pragma unroll
        for (int i = 0; i < 2; i++){
            int e = tid + i*256, r = e >> 4, c = e & 15;
            cpa16(sptr(&Qs[s][r*136 + c*8]), qb + (size_t)(s*32+r)*HWc + c*8);
            cpa16(sptr(&Ks[s][r*136 + c*8]), kb + (size_t)(s*32+r)*HWc + c*8);
        }
        CP_COMMIT();
    }

    float acc[2][8][4] = {};

    #pragma unroll
    for (int st = 0; st < 2; st++){
        if (st == 0) { CP_WAIT(1); } else { CP_WAIT(0); }
        __syncthreads();
        const __half* Qc = Qs[st];
        const __half* Kc = Ks[st];
        #pragma unroll
        for (int ks = 0; ks < 2; ks++){
            uint32_t af[2][4], bfm[4][4];
            #pragma unroll
            for (int mt = 0; mt < 2; mt++){
                int row = ks*16 + (lane >> 4)*8 + (lane & 7);      // A via trans
                int col = wr*32 + mt*16 + ((lane >> 3) & 1)*8;
                ldsm4t(af[mt], sptr(Qc + row*136 + col));
            }
            #pragma unroll
            for (int p = 0; p < 4; p++){
                int krow = ks*16 + ((lane >> 3) & 1)*8 + (lane & 7);
                int ncol = wc*64 + p*16 + (lane >> 4)*8;
                ldsm4t(bfm[p], sptr(Kc + krow*136 + ncol));
            }
            #pragma unroll
            for (int mt = 0; mt < 2; mt++)
                #pragma unroll
                for (int nt = 0; nt < 8; nt++)
                    mma_f16(acc[mt][nt], af[mt], bfm[nt>>1][(nt&1)*2], bfm[nt>>1][(nt&1)*2+1]);
        }
    }
    __half* eb = E + (size_t)bl*HWc;
    #pragma unroll
    for (int mt = 0; mt < 2; mt++)
        #pragma unroll
        for (int nt = 0; nt < 8; nt++){
            int row = wr*32 + mt*16 + (lane >> 2);
            int col = wc*64 + nt*8 + (lane & 3)*2;
            __half2 u0 = __floats2half2_rn(acc[mt][nt][0], acc[mt][nt][1]);
            __half2 u1 = __floats2half2_rn(acc[mt][nt][2], acc[mt][nt][3]);
            *(__half2*)&eb[(size_t)row*128 + col]     = u0;
            *(__half2*)&eb[(size_t)(row+8)*128 + col] = u1;
        }
}

// ---------------- joint softmax: fp16 logits in -> fp16 probs out (in place) --
__global__ void softmax_kernel(__half* __restrict__ eH, __half* __restrict__ eW){
    const int pix  = blockIdx.x*8 + (threadIdx.x >> 5);
    const int lane = threadIdx.x & 31;
    const int w = pix & 127, h = (pix >> 7) & 127, b = pix >> 14;

    const size_t offH = ((size_t)((b*128 + w)*128 + h))*128 + lane*4;
    const size_t offW = ((size_t)((b*128 + h)*128 + w))*128 + lane*4;
    uint2 uh = *(const uint2*)(eH + offH);
    uint2 uw = *(const uint2*)(eW + offW);
    __half2 h0 = *(__half2*)&uh.x, h1 = *(__half2*)&uh.y;
    __half2 w0 = *(__half2*)&uw.x, w1 = *(__half2*)&uw.y;
    float4 vh = { __half2float(h0.x), __half2float(h0.y),
                  __half2float(h1.x), __half2float(h1.y) };
    float4 vw = { __half2float(w0.x), __half2float(w0.y),
                  __half2float(w1.x), __half2float(w1.y) };

    const int d = h - lane*4;
    if (d >= 0 && d < 4) ((float*)&vh)[d] = NEGV;

    float mx = fmaxf(fmaxf(fmaxf(vh.x, vh.y), fmaxf(vh.z, vh.w)),
                     fmaxf(fmaxf(vw.x, vw.y), fmaxf(vw.z, vw.w)));
    #pragma unroll
    for (int o = 16; o; o >>= 1) mx = fmaxf(mx, __shfl_xor_sync(0xffffffffu, mx, o));

    vh.x = __expf(vh.x - mx); vh.y = __expf(vh.y - mx);
    vh.z = __expf(vh.z - mx); vh.w = __expf(vh.w - mx);
    vw.x = __expf(vw.x - mx); vw.y = __expf(vw.y - mx);
    vw.z = __expf(vw.z - mx); vw.w = __expf(vw.w - mx);

    float s = vh.x + vh.y + vh.z + vh.w + vw.x + vw.y + vw.z + vw.w;
    #pragma unroll
    for (int o = 16; o; o >>= 1) s += __shfl_xor_sync(0xffffffffu, s, o);
    const float inv = 1.0f / s;

    float4 ph = { vh.x*inv, vh.y*inv, vh.z*inv, vh.w*inv };
    float4 pw = { vw.x*inv, vw.y*inv, vw.z*inv, vw.w*inv };
    *(uint2*)(eH + offH) = f4_to_h4(ph);
    *(uint2*)(eW + offW) = f4_to_h4(pw);
}

// ---------------- apply: Out[c,i] = sum_j V[c,j]*P[i,j], 2-stage async --------
// blockIdx.z: 0 -> (projT, eH-probs) -> oHt ; 1 -> (proj, eW-probs) -> oW
__global__ void __launch_bounds__(256, 2) apply_f16(
        const __half* __restrict__ proj, const __half* __restrict__ projT,
        const __half* __restrict__ aH, const __half* __restrict__ aW,
        __half* __restrict__ oHt, __half* __restrict__ oW){
    const __half* Vfull = blockIdx.z ? proj : projT;
    const __half* Pm    = blockIdx.z ? aW : aH;
    __half* Outp        = blockIdx.z ? oW : oHt;

    const int bl = blockIdx.y, b = bl >> 7, line = bl & 127;
    const __half* Vb = Vfull + ((size_t)(b*PROJ_M + 128 + blockIdx.x*128))*HWc + line*128;
    const __half* Pb = Pm + (size_t)bl*HWc;
    __half* Ob = Outp + ((size_t)(b*Cch + blockIdx.x*128))*HWc + line*128;

    __shared__ __half Vs[2][128*40];   // [c][j] stride 40
    __shared__ __half Ps[2][128*40];   // [i][j] stride 40

    const int tid = threadIdx.x, lane = tid & 31, warp = tid >> 5;
    const int wr = warp >> 1, wc = warp & 1;

    const __half* vsrc[2]; const __half* psrc[2];
    uint32_t vdst[2][2], pdst[2][2];
    #pragma unroll
    for (int i = 0; i < 2; i++){
        int e = tid + i*256;
        int r = e >> 2, c = e & 3;               // 4 chunks per 32-half row
        vsrc[i] = Vb + (size_t)r*HWc + c*8;
        psrc[i] = Pb + (size_t)r*128 + c*8;
        #pragma unroll
        for (int s = 0; s < 2; s++){
            vdst[s][i] = sptr(&Vs[s][r*40 + c*8]);
            pdst[s][i] = sptr(&Ps[s][r*40 + c*8]);
        }
    }

    float acc[2][8][4] = {};
    const int NIT = 128/32;   // 4

    #pragma unroll
    for (int s = 0; s < 2; s++){
        #pragma unroll
        for (int i = 0; i < 2; i++){
            cpa16(vdst[s][i], vsrc[i] + s*32);
            cpa16(pdst[s][i], psrc[i] + s*32);
        }
        CP_COMMIT();
    }

    for (int it = 0; it < NIT; it++){
        if (it == NIT-1) { CP_WAIT(0); } else { CP_WAIT(1); }
        __syncthreads();
        const int cur = it & 1;
        const __half* Vc = Vs[cur];
        const __half* Pc = Ps[cur];
        #pragma unroll
        for (int ks = 0; ks < 2; ks++){
            uint32_t af[2][4], bfm[4][4];
            #pragma unroll
            for (int mt = 0; mt < 2; mt++){
                int row = wr*32 + mt*16 + (lane & 7) + ((lane >> 3) & 1)*8;
                int col = ks*16 + (lane >> 4)*8;
                ldsm4(af[mt], sptr(Vc + row*40 + col));
            }
            #pragma unroll
            for (int p = 0; p < 4; p++){
                int prow = wc*64 + p*16 + (lane >> 4)*8 + (lane & 7);   // B non-trans
                int pcol = ks*16 + ((lane >> 3) & 1)*8;
                ldsm4(bfm[p], sptr(Pc + prow*40 + pcol));
            }
            #pragma unroll
            for (int mt = 0; mt < 2; mt++)
                #pragma unroll
                for (int nt = 0; nt < 8; nt++)
                    mma_f16(acc[mt][nt], af[mt], bfm[nt>>1][(nt&1)*2], bfm[nt>>1][(nt&1)*2+1]);
        }
        __syncthreads();                 // all warps done reading cur
        if (it + 2 < NIT){               // refill cur for iteration it+2
            const int j0 = (it+2)*32;
            #pragma unroll
            for (int i = 0; i < 2; i++){
                cpa16(vdst[cur][i], vsrc[i] + j0);
                cpa16(pdst[cur][i], psrc[i] + j0);
            }
            CP_COMMIT();
        }
    }
    #pragma unroll
    for (int mt = 0; mt < 2; mt++)
        #pragma unroll
        for (int nt = 0; nt < 8; nt++){
            int row = wr*32 + mt*16 + (lane >> 2);
            int col = wc*64 + nt*8 + (lane & 3)*2;
            __half2 u0 = __floats2half2_rn(acc[mt][nt][0], acc[mt][nt][1]);
            __half2 u1 = __floats2half2_rn(acc[mt][nt][2], acc[mt][nt][3]);
            *(__half2*)(Ob + (size_t)row*HWc + col)     = u0;
            *(__half2*)(Ob + (size_t)(row+8)*HWc + col) = u1;
        }
}

// ---------------- combine: out = gamma*(oHt^T + oW) + xh -----------------------
__global__ void combine_kernel(const __half* __restrict__ oHt, const __half* __restrict__ oW,
                               const __half* __restrict__ xh, const float* __restrict__ gamma,
                               float* __restrict__ out){
    __shared__ __half t[64][65];
    const size_t p = blockIdx.z;
    const __half* hp = oHt + p*HWc;
    const int w0 = blockIdx.x*64, h0 = blockIdx.y*64;
    const int tx = threadIdx.x & 15, ty = threadIdx.x >> 4;
    #pragma unroll
    for (int r = 0; r < 64; r += 16){
        uint2 u = *(const uint2*)(hp + (size_t)(w0+ty+r)*128 + h0 + tx*4);
        __half2 lo = *(__half2*)&u.x, hi = *(__half2*)&u.y;
        __half* d = &t[ty+r][tx*4];
        d[0]=lo.x; d[1]=lo.y; d[2]=hi.x; d[3]=hi.y;
    }
    __syncthreads();
    const float g = gamma[0];
    #pragma unroll
    for (int r = 0; r < 64; r += 16){
        const int h = h0 + ty + r;
        const size_t base = p*HWc + (size_t)h*128 + w0 + tx*4;
        uint2 ux = *(const uint2*)(xh + base);
        __half2 xl = *(__half2*)&ux.x, xhh = *(__half2*)&ux.y;
        uint2 uw = *(const uint2*)(oW + base);
        __half2 lo = *(__half2*)&uw.x, hi = *(__half2*)&uw.y;
        float4 o;
        o.x = g*(__half2float(t[tx*4+0][ty+r]) + __half2float(lo.x)) + __half2float(xl.x);
        o.y = g*(__half2float(t[tx*4+1][ty+r]) + __half2float(lo.y)) + __half2float(xl.y);
        o.z = g*(__half2float(t[tx*4+2][ty+r]) + __half2float(hi.x)) + __half2float(xhh.x);
        o.w = g*(__half2float(t[tx*4+3][ty+r]) + __half2float(hi.y)) + __half2float(xhh.y);
        *(float4*)(out + base) = o;
    }
}

// ---------------------------------------------------------------------------
extern "C" void kernel_launch(void* const* d_in, const int* in_sizes, int n_in,
                              void* d_out, int out_size) {
    (void)in_sizes; (void)n_in; (void)out_size;
    const float* x     = (const float*)d_in[0];
    const float* Wq    = (const float*)d_in[1];
    const float* Wk    = (const float*)d_in[2];
    const float* Wv    = (const float*)d_in[3];
    const float* gamma = (const float*)d_in[4];
    float* out = (float*)d_out;

    __half *xh, *wall, *proj, *projT, *eH, *eW, *oHt, *oW;
    cudaGetSymbolAddress((void**)&xh,   g_xh);
    cudaGetSymbolAddress((void**)&wall, g_wall);
    cudaGetSymbolAddress((void**)&proj, g_proj);
    cudaGetSymbolAddress((void**)&projT,g_projT);
    cudaGetSymbolAddress((void**)&eH,   g_eH);
    cudaGetSymbolAddress((void**)&eW,   g_eW);
    cudaGetSymbolAddress((void**)&oHt,  g_oHt);
    cudaGetSymbolAddress((void**)&oW,   g_oW);

    // 0) fp16 conversion + weight packing (single launch)
    convert_all<<<CONV_BLOCKS + (PROJ_M*Cch)/(256*4), 256>>>(x, xh, Wq, Wk, Wv, wall);

    // 1) fused projection (q|k|v packed), fp16 HMMA, 2-stage / 2 blocks-per-SM
    proj_f16<<<dim3(HWc/128, PROJ_M/128, Bsz), 256>>>(wall, xh, proj);

    // 2) plane transposes (H<->W for all 640 planes per batch), fp16
    transpose_f16<<<dim3(2,2,Bsz*PROJ_M), 256>>>(proj, projT);

    // 3) attention scores -> fp16 logits
    gram_f16<<<dim3(Bsz*128, 2), 256>>>(proj, projT, eH, eW);

    // 4) joint softmax in place: fp16 logits -> fp16 probs
    softmax_kernel<<<(Bsz*HWc)/8, 256>>>(eH, eW);

    // 5) apply attention (z=0 -> oHt, z=1 -> oW), 2-stage / 2 blocks-per-SM
    apply_f16<<<dim3(Cch/128, Bsz*128, 2), 256>>>(proj, projT, eH, eW, oHt, oW);

    // 6) combine (reads fp16 xh)
    combine_kernel<<<dim3(2,2,Bsz*Cch), 256>>>(oHt, oW, xh, gamma, out);
}

// round 15
// speedup vs baseline: 1.1921x; 1.0232x over previous
#include <cuda_runtime.h>
#include <cuda_fp16.h>
#include <cstdint>

#define Bsz 4
#define Cch 512
#define MID 64
#define HWc 16384
#define PROJ_M 640
#define NEGV (-60000.0f)

// ---------------- scratch ----------------------------------------------------
__device__ __align__(16) __half g_xh  [(size_t)Bsz*Cch*HWc];
__device__ __align__(16) __half g_wall[PROJ_M*Cch];
__device__ __align__(16) __half g_proj [(size_t)Bsz*PROJ_M*HWc];
__device__ __align__(16) __half g_projT[(size_t)Bsz*PROJ_M*HWc];
__device__ __align__(16) __half g_eH[(size_t)Bsz*128*HWc];   // fp16 logits -> probs (in place)
__device__ __align__(16) __half g_eW[(size_t)Bsz*128*HWc];
__device__ __align__(16) __half g_oHt[(size_t)Bsz*Cch*HWc];
__device__ __align__(16) __half g_oW [(size_t)Bsz*Cch*HWc];

// ---------------- helpers ------------------------------------------------------
__device__ __forceinline__ uint32_t sptr(const void* p){
    return (uint32_t)__cvta_generic_to_shared(p);
}
__device__ __forceinline__ void cpa16(uint32_t s, const void* g){
    asm volatile("cp.async.ca.shared.global [%0], [%1], 16;" :: "r"(s), "l"(g));
}
#define CP_COMMIT() asm volatile("cp.async.commit_group;")
#define CP_WAIT(n)  asm volatile("cp.async.wait_group %0;" :: "n"(n))

__device__ __forceinline__ void ldsm4(uint32_t* r, uint32_t a){
    asm volatile("ldmatrix.sync.aligned.m8n8.x4.shared.b16 {%0,%1,%2,%3},[%4];"
        : "=r"(r[0]),"=r"(r[1]),"=r"(r[2]),"=r"(r[3]) : "r"(a));
}
__device__ __forceinline__ void ldsm4t(uint32_t* r, uint32_t a){
    asm volatile("ldmatrix.sync.aligned.m8n8.x4.trans.shared.b16 {%0,%1,%2,%3},[%4];"
        : "=r"(r[0]),"=r"(r[1]),"=r"(r[2]),"=r"(r[3]) : "r"(a));
}
__device__ __forceinline__ void mma_f16(float* c, const uint32_t* a, uint32_t b0, uint32_t b1){
    asm volatile(
        "mma.sync.aligned.m16n8k16.row.col.f32.f16.f16.f32 "
        "{%0,%1,%2,%3}, {%4,%5,%6,%7}, {%8,%9}, {%0,%1,%2,%3};"
        : "+f"(c[0]),"+f"(c[1]),"+f"(c[2]),"+f"(c[3])
        : "r"(a[0]),"r"(a[1]),"r"(a[2]),"r"(a[3]),"r"(b0),"r"(b1));
}
__device__ __forceinline__ uint2 f4_to_h4(float4 v){
    __half2 a = __floats2half2_rn(v.x, v.y);
    __half2 b = __floats2half2_rn(v.z, v.w);
    uint2 u; u.x = *(uint32_t*)&a; u.y = *(uint32_t*)&b; return u;
}

// ---------------- conversion + weight pack, single launch ----------------------
#define CONV_BLOCKS ((Bsz*Cch*HWc)/(256*4))      // 32768
__global__ void convert_all(const float* __restrict__ x, __half* __restrict__ xh,
                            const float* __restrict__ Wq, const float* __restrict__ Wk,
                            const float* __restrict__ Wv, __half* __restrict__ wall){
    if (blockIdx.x < CONV_BLOCKS){
        size_t i = ((size_t)blockIdx.x*256 + threadIdx.x)*4;
        *(uint2*)(xh + i) = f4_to_h4(*(const float4*)(x + i));
    } else {
        int i = ((blockIdx.x - CONV_BLOCKS)*256 + threadIdx.x)*4;
        int row = i >> 9, col = i & 511;
        const float* src = row < 64 ? Wq + (size_t)row*512
                         : row < 128 ? Wk + (size_t)(row-64)*512
                                     : Wv + (size_t)(row-128)*512;
        *(uint2*)(wall + i) = f4_to_h4(*(const float4*)(src + col));
    }
}

// ---------------- projection: proj[b] = Wall(640x512) @ xh[b](512x16384) -----
// block 128m x 128n, BK=32, 3-stage cp.async + 2 blocks/SM (57KB smem x2 = 114KB);
// 8 warps (4x2), warp tile 32x64. Single sync/iter, issue-after-sync (race-free).
__global__ void __launch_bounds__(256, 2) proj_f16(
        const __half* __restrict__ Wall, const __half* __restrict__ xh,
        __half* __restrict__ Out){
    const int b = blockIdx.z;
    const int m0blk = blockIdx.y * 128;
    const __half* Bg = xh + (size_t)b*Cch*HWc + blockIdx.x*128;
    __half* Cg = Out + ((size_t)b*PROJ_M + m0blk)*HWc + blockIdx.x*128;

    __shared__ __half As[3][128*40];   // [m][k] stride 40
    __shared__ __half Bs[3][32*136];   // [k][n] stride 136

    const int tid = threadIdx.x, lane = tid & 31, warp = tid >> 5;
    const int wr = warp >> 1, wc = warp & 1;

    const __half* asrc[2]; const __half* bsrc[2];
    uint32_t adst[3][2], bdst[3][2];
    #pragma unroll
    for (int i = 0; i < 2; i++){
        int e = tid + i*256;
        int ra = e >> 2, ca = e & 3;               // A: 4 chunks per 32-half row
        asrc[i] = Wall + (size_t)(m0blk + ra)*Cch + ca*8;
        int rb = e >> 4, cb = e & 15;              // B: 16 chunks per 128-half row
        bsrc[i] = Bg + (size_t)rb*HWc + cb*8;
        #pragma unroll
        for (int s = 0; s < 3; s++){
            adst[s][i] = sptr(&As[s][ra*40 + ca*8]);
            bdst[s][i] = sptr(&Bs[s][rb*136 + cb*8]);
        }
    }

    float acc[2][8][4] = {};
    const int NIT = Cch/32;   // 16

    #pragma unroll
    for (int s = 0; s < 2; s++){
        const int k0 = s*32;
        #pragma unroll
        for (int i = 0; i < 2; i++){
            cpa16(adst[s][i], asrc[i] + k0);
            cpa16(bdst[s][i], bsrc[i] + (size_t)k0*HWc);
        }
        CP_COMMIT();
    }

    for (int it = 0; it < NIT; it++){
        if (it == NIT-1) { CP_WAIT(0); } else { CP_WAIT(1); }
        __syncthreads();
        if (it + 2 < NIT){
            const int s = (it+2) % 3;
            const int k0 = (it+2)*32;
            #pragma unroll
            for (int i = 0; i < 2; i++){
                cpa16(adst[s][i], asrc[i] + k0);
                cpa16(bdst[s][i], bsrc[i] + (size_t)k0*HWc);
            }
            CP_COMMIT();
        }
        const __half* Ac = As[it % 3];
        const __half* Bc = Bs[it % 3];
        #pragma unroll
        for (int ks = 0; ks < 2; ks++){
            uint32_t af[2][4], bfm[4][4];
            #pragma unroll
            for (int mt = 0; mt < 2; mt++){
                int row = wr*32 + mt*16 + (lane & 7) + ((lane >> 3) & 1)*8;
                int col = ks*16 + (lane >> 4)*8;
                ldsm4(af[mt], sptr(Ac + row*40 + col));
            }
            #pragma unroll
            for (int p = 0; p < 4; p++){
                int krow = ks*16 + ((lane >> 3) & 1)*8 + (lane & 7);
                int ncol = wc*64 + p*16 + (lane >> 4)*8;
                ldsm4t(bfm[p], sptr(Bc + krow*136 + ncol));
            }
            #pragma unroll
            for (int mt = 0; mt < 2; mt++)
                #pragma unroll
                for (int nt = 0; nt < 8; nt++)
                    mma_f16(acc[mt][nt], af[mt], bfm[nt>>1][(nt&1)*2], bfm[nt>>1][(nt&1)*2+1]);
        }
    }
    __syncthreads();
    #pragma unroll
    for (int mt = 0; mt < 2; mt++)
        #pragma unroll
        for (int nt = 0; nt < 8; nt++){
            int row = wr*32 + mt*16 + (lane >> 2);
            int col = wc*64 + nt*8 + (lane & 3)*2;
            __half2 u0 = __floats2half2_rn(acc[mt][nt][0], acc[mt][nt][1]);
            __half2 u1 = __floats2half2_rn(acc[mt][nt][2], acc[mt][nt][3]);
            *(__half2*)(Cg + (size_t)row*HWc + col)     = u0;
            *(__half2*)(Cg + (size_t)(row+8)*HWc + col) = u1;
        }
}

// ---------------- 128x128 fp16 plane transpose (64x64 tiles) ------------------
__global__ void transpose_f16(const __half* __restrict__ in, __half* __restrict__ out){
    __shared__ __half t[64][65];
    const size_t p = blockIdx.z;
    const __half* ip = in + p*HWc;
    __half* op = out + p*HWc;
    const int x0 = blockIdx.x*64, y0 = blockIdx.y*64;
    const int tx = threadIdx.x & 15, ty = threadIdx.x >> 4;
    #pragma unroll
    for (int r = 0; r < 64; r += 16){
        uint2 u = *(const uint2*)(ip + (size_t)(y0+ty+r)*128 + x0 + tx*4);
        __half2 lo = *(__half2*)&u.x, hi = *(__half2*)&u.y;
        __half* d = &t[ty+r][tx*4];
        d[0]=lo.x; d[1]=lo.y; d[2]=hi.x; d[3]=hi.y;
    }
    __syncthreads();
    #pragma unroll
    for (int r = 0; r < 64; r += 16){
        __half2 lo, hi;
        lo.x = t[tx*4+0][ty+r]; lo.y = t[tx*4+1][ty+r];
        hi.x = t[tx*4+2][ty+r]; hi.y = t[tx*4+3][ty+r];
        uint2 u; u.x = *(uint32_t*)&lo; u.y = *(uint32_t*)&hi;
        *(uint2*)(op + (size_t)(x0+ty+r)*128 + y0 + tx*4) = u;
    }
}

// ---------------- gram: E[i,j] = sum_m Q[m,i]*K[m,j] -> fp16 logits -----------
// blockIdx.y: 0 -> eH from projT, 1 -> eW from proj
__global__ void gram_f16(const __half* __restrict__ proj, const __half* __restrict__ projT,
                         __half* __restrict__ eH, __half* __restrict__ eW){
    const __half* P = blockIdx.y ? proj : projT;
    __half* E = blockIdx.y ? eW : eH;
    const int bl = blockIdx.x, b = bl >> 7, line = bl & 127;
    const __half* qb = P + (size_t)(b*PROJ_M)*HWc + line*128;
    const __half* kb = qb + (size_t)MID*HWc;

    __shared__ __half Qs[2][32*136];
    __shared__ __half Ks[2][32*136];

    const int tid = threadIdx.x, lane = tid & 31, warp = tid >> 5;
    const int wr = warp >> 1, wc = warp & 1;

    #pragma unroll
    for (int s = 0; s < 2; s++){
        #pragma unroll
        for (int i = 0; i < 2; i++){
            int e = tid + i*256, r = e >> 4, c = e & 15;
            cpa16(sptr(&Qs[s][r*136 + c*8]), qb + (size_t)(s*32+r)*HWc + c*8);
            cpa16(sptr(&Ks[s][r*136 + c*8]), kb + (size_t)(s*32+r)*HWc + c*8);
        }
        CP_COMMIT();
    }

    float acc[2][8][4] = {};

    #pragma unroll
    for (int st = 0; st < 2; st++){
        if (st == 0) { CP_WAIT(1); } else { CP_WAIT(0); }
        __syncthreads();
        const __half* Qc = Qs[st];
        const __half* Kc = Ks[st];
        #pragma unroll
        for (int ks = 0; ks < 2; ks++){
            uint32_t af[2][4], bfm[4][4];
            #pragma unroll
            for (int mt = 0; mt < 2; mt++){
                int row = ks*16 + (lane >> 4)*8 + (lane & 7);      // A via trans
                int col = wr*32 + mt*16 + ((lane >> 3) & 1)*8;
                ldsm4t(af[mt], sptr(Qc + row*136 + col));
            }
            #pragma unroll
            for (int p = 0; p < 4; p++){
                int krow = ks*16 + ((lane >> 3) & 1)*8 + (lane & 7);
                int ncol = wc*64 + p*16 + (lane >> 4)*8;
                ldsm4t(bfm[p], sptr(Kc + krow*136 + ncol));
            }
            #pragma unroll
            for (int mt = 0; mt < 2; mt++)
                #pragma unroll
                for (int nt = 0; nt < 8; nt++)
                    mma_f16(acc[mt][nt], af[mt], bfm[nt>>1][(nt&1)*2], bfm[nt>>1][(nt&1)*2+1]);
        }
    }
    __half* eb = E + (size_t)bl*HWc;
    #pragma unroll
    for (int mt = 0; mt < 2; mt++)
        #pragma unroll
        for (int nt = 0; nt < 8; nt++){
            int row = wr*32 + mt*16 + (lane >> 2);
            int col = wc*64 + nt*8 + (lane & 3)*2;
            __half2 u0 = __floats2half2_rn(acc[mt][nt][0], acc[mt][nt][1]);
            __half2 u1 = __floats2half2_rn(acc[mt][nt][2], acc[mt][nt][3]);
            *(__half2*)&eb[(size_t)row*128 + col]     = u0;
            *(__half2*)&eb[(size_t)(row+8)*128 + col] = u1;
        }
}

// ---------------- joint softmax: fp16 logits in -> fp16 probs out (in place) --
__global__ void softmax_kernel(__half* __restrict__ eH, __half* __restrict__ eW){
    const int pix  = blockIdx.x*8 + (threadIdx.x >> 5);
    const int lane = threadIdx.x & 31;
    const int w = pix & 127, h = (pix >> 7) & 127, b = pix >> 14;

    const size_t offH = ((size_t)((b*128 + w)*128 + h))*128 + lane*4;
    const size_t offW = ((size_t)((b*128 + h)*128 + w))*128 + lane*4;
    uint2 uh = *(const uint2*)(eH + offH);
    uint2 uw = *(const uint2*)(eW + offW);
    __half2 h0 = *(__half2*)&uh.x, h1 = *(__half2*)&uh.y;
    __half2 w0 = *(__half2*)&uw.x, w1 = *(__half2*)&uw.y;
    float4 vh = { __half2float(h0.x), __half2float(h0.y),
                  __half2float(h1.x), __half2float(h1.y) };
    float4 vw = { __half2float(w0.x), __half2float(w0.y),
                  __half2float(w1.x), __half2float(w1.y) };

    const int d = h - lane*4;
    if (d >= 0 && d < 4) ((float*)&vh)[d] = NEGV;

    float mx = fmaxf(fmaxf(fmaxf(vh.x, vh.y), fmaxf(vh.z, vh.w)),
                     fmaxf(fmaxf(vw.x, vw.y), fmaxf(vw.z, vw.w)));
    #pragma unroll
    for (int o = 16; o; o >>= 1) mx = fmaxf(mx, __shfl_xor_sync(0xffffffffu, mx, o));

    vh.x = __expf(vh.x - mx); vh.y = __expf(vh.y - mx);
    vh.z = __expf(vh.z - mx); vh.w = __expf(vh.w - mx);
    vw.x = __expf(vw.x - mx); vw.y = __expf(vw.y - mx);
    vw.z = __expf(vw.z - mx); vw.w = __expf(vw.w - mx);

    float s = vh.x + vh.y + vh.z + vh.w + vw.x + vw.y + vw.z + vw.w;
    #pragma unroll
    for (int o = 16; o; o >>= 1) s += __shfl_xor_sync(0xffffffffu, s, o);
    const float inv = 1.0f / s;

    float4 ph = { vh.x*inv, vh.y*inv, vh.z*inv, vh.w*inv };
    float4 pw = { vw.x*inv, vw.y*inv, vw.z*inv, vw.w*inv };
    *(uint2*)(eH + offH) = f4_to_h4(ph);
    *(uint2*)(eW + offW) = f4_to_h4(pw);
}

// ---------------- apply: Out[c,i] = sum_j V[c,j]*P[i,j], 3-stage + 2 blk/SM ---
// blockIdx.z: 0 -> (projT, eH-probs) -> oHt ; 1 -> (proj, eW-probs) -> oW
__global__ void __launch_bounds__(256, 2) apply_f16(
        const __half* __restrict__ proj, const __half* __restrict__ projT,
        const __half* __restrict__ aH, const __half* __restrict__ aW,
        __half* __restrict__ oHt, __half* __restrict__ oW){
    const __half* Vfull = blockIdx.z ? proj : projT;
    const __half* Pm    = blockIdx.z ? aW : aH;
    __half* Outp        = blockIdx.z ? oW : oHt;

    const int bl = blockIdx.y, b = bl >> 7, line = bl & 127;
    const __half* Vb = Vfull + ((size_t)(b*PROJ_M + 128 + blockIdx.x*128))*HWc + line*128;
    const __half* Pb = Pm + (size_t)bl*HWc;
    __half* Ob = Outp + ((size_t)(b*Cch + blockIdx.x*128))*HWc + line*128;

    __shared__ __half Vs[3][128*40];   // [c][j] stride 40
    __shared__ __half Ps[3][128*40];   // [i][j] stride 40

    const int tid = threadIdx.x, lane = tid & 31, warp = tid >> 5;
    const int wr = warp >> 1, wc = warp & 1;

    const __half* vsrc[2]; const __half* psrc[2];
    uint32_t vdst[3][2], pdst[3][2];
    #pragma unroll
    for (int i = 0; i < 2; i++){
        int e = tid + i*256;
        int r = e >> 2, c = e & 3;               // 4 chunks per 32-half row
        vsrc[i] = Vb + (size_t)r*HWc + c*8;
        psrc[i] = Pb + (size_t)r*128 + c*8;
        #pragma unroll
        for (int s = 0; s < 3; s++){
            vdst[s][i] = sptr(&Vs[s][r*40 + c*8]);
            pdst[s][i] = sptr(&Ps[s][r*40 + c*8]);
        }
    }

    float acc[2][8][4] = {};
    const int NIT = 128/32;   // 4

    #pragma unroll
    for (int s = 0; s < 2; s++){
        #pragma unroll
        for (int i = 0; i < 2; i++){
            cpa16(vdst[s][i], vsrc[i] + s*32);
            cpa16(pdst[s][i], psrc[i] + s*32);
        }
        CP_COMMIT();
    }

    for (int it = 0; it < NIT; it++){
        if (it == NIT-1) { CP_WAIT(0); } else { CP_WAIT(1); }
        __syncthreads();
        if (it + 2 < NIT){
            const int s = (it+2) % 3;
            const int j0 = (it+2)*32;
            #pragma unroll
            for (int i = 0; i < 2; i++){
                cpa16(vdst[s][i], vsrc[i] + j0);
                cpa16(pdst[s][i], psrc[i] + j0);
            }
            CP_COMMIT();
        }
        const __half* Vc = Vs[it % 3];
        const __half* Pc = Ps[it % 3];
        #pragma unroll
        for (int ks = 0; ks < 2; ks++){
            uint32_t af[2][4], bfm[4][4];
            #pragma unroll
            for (int mt = 0; mt < 2; mt++){
                int row = wr*32 + mt*16 + (lane & 7) + ((lane >> 3) & 1)*8;
                int col = ks*16 + (lane >> 4)*8;
                ldsm4(af[mt], sptr(Vc + row*40 + col));
            }
            #pragma unroll
            for (int p = 0; p < 4; p++){
                int prow = wc*64 + p*16 + (lane >> 4)*8 + (lane & 7);   // B non-trans
                int pcol = ks*16 + ((lane >> 3) & 1)*8;
                ldsm4(bfm[p], sptr(Pc + prow*40 + pcol));
            }
            #pragma unroll
            for (int mt = 0; mt < 2; mt++)
                #pragma unroll
                for (int nt = 0; nt < 8; nt++)
                    mma_f16(acc[mt][nt], af[mt], bfm[nt>>1][(nt&1)*2], bfm[nt>>1][(nt&1)*2+1]);
        }
    }
    __syncthreads();
    #pragma unroll
    for (int mt = 0; mt < 2; mt++)
        #pragma unroll
        for (int nt = 0; nt < 8; nt++){
            int row = wr*32 + mt*16 + (lane >> 2);
            int col = wc*64 + nt*8 + (lane & 3)*2;
            __half2 u0 = __floats2half2_rn(acc[mt][nt][0], acc[mt][nt][1]);
            __half2 u1 = __floats2half2_rn(acc[mt][nt][2], acc[mt][nt][3]);
            *(__half2*)(Ob + (size_t)row*HWc + col)     = u0;
            *(__half2*)(Ob + (size_t)(row+8)*HWc + col) = u1;
        }
}

// ---------------- combine: out = gamma*(oHt^T + oW) + xh -----------------------
__global__ void combine_kernel(const __half* __restrict__ oHt, const __half* __restrict__ oW,
                               const __half* __restrict__ xh, const float* __restrict__ gamma,
                               float* __restrict__ out){
    __shared__ __half t[64][65];
    const size_t p = blockIdx.z;
    const __half* hp = oHt + p*HWc;
    const int w0 = blockIdx.x*64, h0 = blockIdx.y*64;
    const int tx = threadIdx.x & 15, ty = threadIdx.x >> 4;
    #pragma unroll
    for (int r = 0; r < 64; r += 16){
        uint2 u = *(const uint2*)(hp + (size_t)(w0+ty+r)*128 + h0 + tx*4);
        __half2 lo = *(__half2*)&u.x, hi = *(__half2*)&u.y;
        __half* d = &t[ty+r][tx*4];
        d[0]=lo.x; d[1]=lo.y; d[2]=hi.x; d[3]=hi.y;
    }
    __syncthreads();
    const float g = gamma[0];
    #pragma unroll
    for (int r = 0; r < 64; r += 16){
        const int h = h0 + ty + r;
        const size_t base = p*HWc + (size_t)h*128 + w0 + tx*4;
        uint2 ux = *(const uint2*)(xh + base);
        __half2 xl = *(__half2*)&ux.x, xhh = *(__half2*)&ux.y;
        uint2 uw = *(const uint2*)(oW + base);
        __half2 lo = *(__half2*)&uw.x, hi = *(__half2*)&uw.y;
        float4 o;
        o.x = g*(__half2float(t[tx*4+0][ty+r]) + __half2float(lo.x)) + __half2float(xl.x);
        o.y = g*(__half2float(t[tx*4+1][ty+r]) + __half2float(lo.y)) + __half2float(xl.y);
        o.z = g*(__half2float(t[tx*4+2][ty+r]) + __half2float(hi.x)) + __half2float(xhh.x);
        o.w = g*(__half2float(t[tx*4+3][ty+r]) + __half2float(hi.y)) + __half2float(xhh.y);
        *(float4*)(out + base) = o;
    }
}

// ---------------------------------------------------------------------------
extern "C" void kernel_launch(void* const* d_in, const int* in_sizes, int n_in,
                              void* d_out, int out_size) {
    (void)in_sizes; (void)n_in; (void)out_size;
    const float* x     = (const float*)d_in[0];
    const float* Wq    = (const float*)d_in[1];
    const float* Wk    = (const float*)d_in[2];
    const float* Wv    = (const float*)d_in[3];
    const float* gamma = (const float*)d_in[4];
    float* out = (float*)d_out;

    __half *xh, *wall, *proj, *projT, *eH, *eW, *oHt, *oW;
    cudaGetSymbolAddress((void**)&xh,   g_xh);
    cudaGetSymbolAddress((void**)&wall, g_wall);
    cudaGetSymbolAddress((void**)&proj, g_proj);
    cudaGetSymbolAddress((void**)&projT,g_projT);
    cudaGetSymbolAddress((void**)&eH,   g_eH);
    cudaGetSymbolAddress((void**)&eW,   g_eW);
    cudaGetSymbolAddress((void**)&oHt,  g_oHt);
    cudaGetSymbolAddress((void**)&oW,   g_oW);

    // 0) fp16 conversion + weight packing (single launch)
    convert_all<<<CONV_BLOCKS + (PROJ_M*Cch)/(256*4), 256>>>(x, xh, Wq, Wk, Wv, wall);

    // 1) fused projection (q|k|v packed), fp16 HMMA, 3-stage + 2 blocks/SM
    proj_f16<<<dim3(HWc/128, PROJ_M/128, Bsz), 256>>>(wall, xh, proj);

    // 2) plane transposes (H<->W for all 640 planes per batch), fp16
    transpose_f16<<<dim3(2,2,Bsz*PROJ_M), 256>>>(proj, projT);

    // 3) attention scores -> fp16 logits
    gram_f16<<<dim3(Bsz*128, 2), 256>>>(proj, projT, eH, eW);

    // 4) joint softmax in place: fp16 logits -> fp16 probs
    softmax_kernel<<<(Bsz*HWc)/8, 256>>>(eH, eW);

    // 5) apply attention (z=0 -> oHt, z=1 -> oW), 3-stage + 2 blocks/SM
    apply_f16<<<dim3(Cch/128, Bsz*128, 2), 256>>>(proj, projT, eH, eW, oHt, oW);

    // 6) combine (reads fp16 xh)
    combine_kernel<<<dim3(2,2,Bsz*Cch), 256>>>(oHt, oW, xh, gamma, out);
}